// round 10
// baseline (speedup 1.0000x reference)
#include <cuda_runtime.h>
#include <math.h>

#define NN   2048
#define BB   8
#define HH   4
#define DD   64
#define SEG1 (BB*HH)     // 32 segments in layer 1
#define CH   32          // scan chunks per segment
#define CL   (NN/CH)     // 64 elements per chunk
#define ALPHA_ 0.2f

// ---------------- scratch (static __device__, no allocation) ----------------
__device__ float g_Hbuf [SEG1 * NN * DD];
__device__ float g_H2   [BB   * NN * DD];
__device__ float g_s1   [SEG1 * NN];
__device__ float g_s2   [SEG1 * NN];
__device__ float g_sorted[SEG1 * NN];
__device__ int   g_perm [SEG1 * NN];
__device__ float g_wpre [SEG1 * NN];
__device__ float g_wsuf [SEG1 * NN];
__device__ float g_smax [SEG1];
__device__ float g_CT   [SEG1 * CH * 128];     // chunk offsets (A: 0-63, B: 64-127)
__device__ float g_A1   [SEG1 * (NN+1)];
__device__ float g_B1   [SEG1 * (NN+1)];
__device__ float g_AhN  [SEG1 * DD];           // vector totals of wpre*h
__device__ float g_XC   [BB * NN * HH * DD];
__device__ int   g_qp   [SEG1 * NN];
__device__ float2 g_qr  [SEG1 * NN];
__device__ int   g_binCount[SEG1 * CH];
__device__ int   g_binList [SEG1 * CH * NN];

// ---------------- layer-1 GEMM: all 4 heads per block, X tile reused ----------------
__global__ __launch_bounds__(256)
void gemm1_kernel(const float* __restrict__ X,
                  const float* __restrict__ Wmat,
                  const float* __restrict__ avec) {
    __shared__ float XsT[64][68];
    __shared__ float Ws [64][64];
    const int tid = threadIdx.x;
    const int R0  = blockIdx.x * 64;
    const int rq  = tid >> 4;
    const int cq  = tid & 15;

#pragma unroll
    for (int i = 0; i < 16; i++) {
        int idx = tid + i * 256;
        int r = idx >> 6, k = idx & 63;
        XsT[k][r] = X[(size_t)(R0 + r) * 64 + k];
    }

    for (int head = 0; head < HH; head++) {
        __syncthreads();
#pragma unroll
        for (int i = 0; i < 16; i++) {
            int idx = tid + i * 256;
            int k = idx >> 6, d = idx & 63;
            Ws[k][d] = Wmat[((size_t)head * 64 + k) * 64 + d];
        }
        __syncthreads();

        float acc[4][4];
#pragma unroll
        for (int i = 0; i < 4; i++)
#pragma unroll
            for (int j = 0; j < 4; j++) acc[i][j] = 0.f;

#pragma unroll 16
        for (int k = 0; k < 64; k++) {
            float4 xv = *(const float4*)&XsT[k][rq * 4];
            float4 wv = *(const float4*)&Ws [k][cq * 4];
            acc[0][0] += xv.x*wv.x; acc[0][1] += xv.x*wv.y; acc[0][2] += xv.x*wv.z; acc[0][3] += xv.x*wv.w;
            acc[1][0] += xv.y*wv.x; acc[1][1] += xv.y*wv.y; acc[1][2] += xv.y*wv.z; acc[1][3] += xv.y*wv.w;
            acc[2][0] += xv.z*wv.x; acc[2][1] += xv.z*wv.y; acc[2][2] += xv.z*wv.z; acc[2][3] += xv.z*wv.w;
            acc[3][0] += xv.w*wv.x; acc[3][1] += xv.w*wv.y; acc[3][2] += xv.w*wv.z; acc[3][3] += xv.w*wv.w;
        }

        float a1v[4], a2v[4];
#pragma unroll
        for (int j = 0; j < 4; j++) {
            a1v[j] = __ldg(&avec[head * 128 + cq * 4 + j]);
            a2v[j] = __ldg(&avec[head * 128 + 64 + cq * 4 + j]);
        }
#pragma unroll
        for (int i = 0; i < 4; i++) {
            int R = R0 + rq * 4 + i;
            int g = R >> 11;
            int n = R & (NN - 1);
            int seg = g * HH + head;
            size_t base = ((size_t)seg * NN + n) * 64 + cq * 4;
            float4 v; v.x = acc[i][0]; v.y = acc[i][1]; v.z = acc[i][2]; v.w = acc[i][3];
            *(float4*)&g_Hbuf[base] = v;

            float p1 = acc[i][0]*a1v[0] + acc[i][1]*a1v[1] + acc[i][2]*a1v[2] + acc[i][3]*a1v[3];
            float p2 = acc[i][0]*a2v[0] + acc[i][1]*a2v[1] + acc[i][2]*a2v[2] + acc[i][3]*a2v[3];
#pragma unroll
            for (int off = 8; off; off >>= 1) {
                p1 += __shfl_down_sync(0xffffffffu, p1, off, 16);
                p2 += __shfl_down_sync(0xffffffffu, p2, off, 16);
            }
            if (cq == 0) {
                g_s1[seg * NN + n] = p1;
                g_s2[seg * NN + n] = p2;
            }
        }
    }
}

// ---------------- layer-2 GEMM (K = 256) ----------------
__global__ __launch_bounds__(256)
void gemm2_kernel(const float* __restrict__ Wmat,
                  const float* __restrict__ avec) {
    __shared__ float XsT[64][68];
    __shared__ float Ws [64][64];
    const int tid = threadIdx.x;
    const int R0  = blockIdx.x * 64;
    const int rq  = tid >> 4;
    const int cq  = tid & 15;

    float acc[4][4];
#pragma unroll
    for (int i = 0; i < 4; i++)
#pragma unroll
        for (int j = 0; j < 4; j++) acc[i][j] = 0.f;

    for (int kp = 0; kp < 256; kp += 64) {
        __syncthreads();
#pragma unroll
        for (int i = 0; i < 16; i++) {
            int idx = tid + i * 256;
            int r = idx >> 6, k = idx & 63;
            XsT[k][r] = g_XC[(size_t)(R0 + r) * 256 + kp + k];
        }
#pragma unroll
        for (int i = 0; i < 16; i++) {
            int idx = tid + i * 256;
            int k = idx >> 6, d = idx & 63;
            Ws[k][d] = Wmat[((size_t)kp + k) * 64 + d];
        }
        __syncthreads();
#pragma unroll 16
        for (int k = 0; k < 64; k++) {
            float4 xv = *(const float4*)&XsT[k][rq * 4];
            float4 wv = *(const float4*)&Ws [k][cq * 4];
            acc[0][0] += xv.x*wv.x; acc[0][1] += xv.x*wv.y; acc[0][2] += xv.x*wv.z; acc[0][3] += xv.x*wv.w;
            acc[1][0] += xv.y*wv.x; acc[1][1] += xv.y*wv.y; acc[1][2] += xv.y*wv.z; acc[1][3] += xv.y*wv.w;
            acc[2][0] += xv.z*wv.x; acc[2][1] += xv.z*wv.y; acc[2][2] += xv.z*wv.z; acc[2][3] += xv.z*wv.w;
            acc[3][0] += xv.w*wv.x; acc[3][1] += xv.w*wv.y; acc[3][2] += xv.w*wv.z; acc[3][3] += xv.w*wv.w;
        }
    }

    float a1v[4], a2v[4];
#pragma unroll
    for (int j = 0; j < 4; j++) {
        a1v[j] = __ldg(&avec[cq * 4 + j]);
        a2v[j] = __ldg(&avec[64 + cq * 4 + j]);
    }
#pragma unroll
    for (int i = 0; i < 4; i++) {
        int R = R0 + rq * 4 + i;
        int seg = R >> 11;
        int n = R & (NN - 1);
        size_t base = ((size_t)seg * NN + n) * 64 + cq * 4;
        float4 v; v.x = acc[i][0]; v.y = acc[i][1]; v.z = acc[i][2]; v.w = acc[i][3];
        *(float4*)&g_H2[base] = v;

        float p1 = acc[i][0]*a1v[0] + acc[i][1]*a1v[1] + acc[i][2]*a1v[2] + acc[i][3]*a1v[3];
        float p2 = acc[i][0]*a2v[0] + acc[i][1]*a2v[1] + acc[i][2]*a2v[2] + acc[i][3]*a2v[3];
#pragma unroll
        for (int off = 8; off; off >>= 1) {
            p1 += __shfl_down_sync(0xffffffffu, p1, off, 16);
            p2 += __shfl_down_sync(0xffffffffu, p2, off, 16);
        }
        if (cq == 0) {
            g_s1[seg * NN + n] = p1;
            g_s2[seg * NN + n] = p2;
        }
    }
}

// ---------------- bitonic sort ----------------
__global__ __launch_bounds__(1024)
void sort_kernel() {
    __shared__ float key[NN];
    __shared__ int   idx[NN];
    const int seg = blockIdx.x, tid = threadIdx.x;

    key[tid]        = g_s2[seg * NN + tid];        idx[tid]        = tid;
    key[tid + 1024] = g_s2[seg * NN + tid + 1024]; idx[tid + 1024] = tid + 1024;

    for (int k = 2; k <= NN; k <<= 1) {
        for (int j = k >> 1; j > 0; j >>= 1) {
            __syncthreads();
            int i = ((tid & ~(j - 1)) << 1) | (tid & (j - 1));
            int p = i | j;
            bool up = ((i & k) == 0);
            float ka = key[i], kb = key[p];
            if ((ka > kb) == up) {
                key[i] = kb; key[p] = ka;
                int t = idx[i]; idx[i] = idx[p]; idx[p] = t;
            }
        }
    }
    __syncthreads();

    float smaxv = key[NN - 1];
#pragma unroll
    for (int u = 0; u < 2; u++) {
        int i = tid + u * 1024;
        float kk = key[i];
        g_sorted[seg * NN + i] = kk;
        g_perm  [seg * NN + i] = idx[i];
        g_wsuf  [seg * NN + i] = expf(kk - smaxv);
        g_wpre  [seg * NN + i] = expf(ALPHA_ * (kk - smaxv));
    }
    if (tid == 0) g_smax[seg] = smaxv;
}

// ---------------- fused 3a+3b: chunk sums + all scans, one block per segment ----------------
__global__ __launch_bounds__(1024)
void fuse3ab_kernel(int layer) {
    __shared__ int   sperm[NN];
    __shared__ float sA[NN], sB[NN];
    __shared__ float sCT[CH * 128];
    __shared__ float wtotA[32], wtmpA[32], wtotB[32], wtmpB[32];

    const int seg = blockIdx.x, tid = threadIdx.x;
    const float* __restrict__ H = (layer == 1) ? g_Hbuf : g_H2;

#pragma unroll
    for (int i = 0; i < 2; i++) {
        int idx = tid + i * 1024;
        sperm[idx] = g_perm[seg * NN + idx];
        sA[idx]    = g_wpre[seg * NN + idx];
        sB[idx]    = g_wsuf[seg * NN + idx];
    }
    if (tid < CH) g_binCount[seg * CH + tid] = 0;
    __syncthreads();

    // chunk sums: 2048 (chunk,d) tasks, 2 per thread
    const size_t segNN = (size_t)seg * NN;
#pragma unroll
    for (int rep = 0; rep < 2; rep++) {
        int task = tid + rep * 1024;
        int c = task >> 6, d = task & 63;
        int qb = c * CL;
        float accA = 0.f, accB = 0.f;
#pragma unroll 8
        for (int q = 0; q < CL; q++) {
            float h = __ldg(&H[(segNN + sperm[qb + q]) * 64 + d]);
            accA += sA[qb + q] * h;
            accB += sB[qb + q] * h;
        }
        sCT[c * 128 + d]      = accA;
        sCT[c * 128 + 64 + d] = accB;
    }
    __syncthreads();

    // chunk offset scans -> g_CT, A totals -> g_AhN
    if (tid < 64) {
        int d = tid; float run = 0.f;
        for (int c = 0; c < CH; c++) {
            float t = sCT[c * 128 + d];
            g_CT[(seg * CH + c) * 128 + d] = run; run += t;
        }
        g_AhN[seg * 64 + d] = run;
    } else if (tid < 128) {
        int d = tid - 64; float run = 0.f;
        for (int c = CH - 1; c >= 0; c--) {
            float t = sCT[c * 128 + 64 + d];
            g_CT[(seg * CH + c) * 128 + 64 + d] = run; run += t;
        }
    }

    // scalar scans: 2 elements per thread
    const int j0 = tid * 2;
    const int lane = tid & 31, wid = tid >> 5;
    float wa0 = sA[j0], wa1 = sA[j0 + 1];
    float wb0 = sB[j0], wb1 = sB[j0 + 1];
    float saT = wa0 + wa1;
    float sbT = wb0 + wb1;

    float xa = saT;
#pragma unroll
    for (int off = 1; off < 32; off <<= 1) {
        float y = __shfl_up_sync(0xffffffffu, xa, off);
        if (lane >= off) xa += y;
    }
    float exA = xa - saT;
    float xb = sbT;
#pragma unroll
    for (int off = 1; off < 32; off <<= 1) {
        float y = __shfl_down_sync(0xffffffffu, xb, off);
        if (lane < 32 - off) xb += y;
    }
    float exB = xb - sbT;

    if (lane == 31) wtotA[wid] = xa;
    if (lane == 0)  wtotB[wid] = xb;
    __syncthreads();
    if (tid == 0) {
        float r = 0.f;
        for (int w = 0; w < 32; w++) { float t = wtotA[w]; wtmpA[w] = r; r += t; }
        g_A1[seg * (NN + 1) + NN] = r;
        r = 0.f;
        for (int w = 31; w >= 0; w--) { float t = wtotB[w]; wtmpB[w] = r; r += t; }
        g_B1[seg * (NN + 1) + NN] = 0.f;
    }
    __syncthreads();
    float oa = wtmpA[wid] + exA;
    float ob = wtmpB[wid] + exB;
    g_A1[seg * (NN + 1) + j0]     = oa;
    g_A1[seg * (NN + 1) + j0 + 1] = oa + wa0;
    g_B1[seg * (NN + 1) + j0]     = ob + wb0 + wb1;
    g_B1[seg * (NN + 1) + j0 + 1] = ob + wb1;
}

// ---------------- qprep: binary search + factor precompute + chunk binning ----------------
__global__ __launch_bounds__(256)
void qprep_kernel() {
    const int seg = blockIdx.x, tid = threadIdx.x;
    const int n = blockIdx.y * 256 + tid;

    __shared__ float srt[NN];
#pragma unroll
    for (int i = 0; i < 8; i++) srt[tid + 256 * i] = g_sorted[seg * NN + tid + 256 * i];
    __syncthreads();

    float s1v  = g_s1[seg * NN + n];
    float smax = g_smax[seg];
    float u = s1v + smax;
    float m = (u >= 0.f) ? u : ALPHA_ * u;
    float f1 = expf(u - m);
    float f2 = expf(ALPHA_ * u - m);
    float tau = -s1v;
    int lo = 0, hi = NN;
    while (lo < hi) {
        int mid = (lo + hi) >> 1;
        if (srt[mid] < tau) lo = mid + 1; else hi = mid;
    }
    int p = lo;
    float A1v = __ldg(&g_A1[seg * (NN + 1) + p]);
    float B1v = __ldg(&g_B1[seg * (NN + 1) + p]);
    float den = f1 * B1v + f2 * A1v;
    g_qp[seg * NN + n] = p;
    g_qr[seg * NN + n] = make_float2(f2 / den, f1 / den);

    int c = p >> 6;                 // CL == 64
    if (c >= CH) c = CH - 1;        // p == NN
    int slot = atomicAdd(&g_binCount[seg * CH + c], 1);
    g_binList[(seg * CH + c) * NN + slot] = n;
}

// ---------------- fused 3c + combine: smem scans, emit outputs for binned queries ----------------
__global__ __launch_bounds__(128)
void combine_kernel(int layer, float* __restrict__ out) {
    const int seg = blockIdx.x, c = blockIdx.y, tid = threadIdx.x;
    const float* __restrict__ H = (layer == 1) ? g_Hbuf : g_H2;
    const int q0 = c * CL;

    __shared__ int   sp[CL];
    __shared__ float swA[CL], swB[CL];
    __shared__ float sAh[(CL + 1) * 64];
    __shared__ float sBt[(CL + 1) * 64];   // tile, becomes Bh after in-place backward scan
    __shared__ float red[8];

    if (tid < 64) {
        sp [tid] = g_perm[seg * NN + q0 + tid];
        swA[tid] = g_wpre[seg * NN + q0 + tid];
    } else {
        swB[tid - 64] = g_wsuf[seg * NN + q0 + tid - 64];
    }
    __syncthreads();

    const size_t segNN = (size_t)seg * NN;
#pragma unroll
    for (int i = 0; i < 32; i++) {
        int lin = tid + 128 * i;
        int q = lin >> 6, d = lin & 63;
        sBt[lin] = __ldg(&H[(segNN + sp[q]) * 64 + d]);
    }
    __syncthreads();

    const int d = tid & 63;
    if (tid < 64) {   // forward exclusive prefix of wpre*h -> sAh
        float run = g_CT[(seg * CH + c) * 128 + d];
#pragma unroll 8
        for (int t = 0; t < CL; t++) {
            sAh[t * 64 + d] = run;
            run += swA[t] * sBt[t * 64 + d];
        }
        sAh[CL * 64 + d] = run;     // prefix at q0+CL (== total for last chunk)
    }
    __syncthreads();                 // forward must finish before tile is overwritten
    if (tid < 64) {   // backward inclusive suffix of wsuf*h, in place over tile
        float run = g_CT[(seg * CH + c) * 128 + 64 + d];
        sBt[CL * 64 + d] = run;     // suffix at q0+CL
#pragma unroll 8
        for (int t = CL - 1; t >= 0; t--) {
            float h = sBt[t * 64 + d];
            run += swB[t] * h;
            sBt[t * 64 + d] = run;
        }
    }
    __syncthreads();

    const int nq   = g_binCount[seg * CH + c];
    const int half = tid >> 6;
    const int lane = tid & 31, wid = tid >> 5;

    for (int base = 0; base < nq; base += 2) {
        int qi = base + half;
        bool valid = qi < nq;
        int n = 0; float o = 0.f;
        if (valid) {
            n = __ldg(&g_binList[(seg * CH + c) * NN + qi]);
            int p = g_qp[seg * NN + n];
            float2 r = g_qr[seg * NN + n];
            int t = p - q0;
            float a = sAh[t * 64 + d];
            float b = sBt[t * 64 + d];
            o = r.y * b + r.x * a;
            o = (o > 0.f) ? o : expm1f(o);
        }
        if (layer == 1) {
            if (valid) {
                int g = seg >> 2, h = seg & 3;
                g_XC[((size_t)g * NN + n) * (HH * DD) + h * DD + d] = o;
            }
        } else {
            float m = valid ? o : -INFINITY;
#pragma unroll
            for (int off = 16; off; off >>= 1) m = fmaxf(m, __shfl_xor_sync(0xffffffffu, m, off));
            if (lane == 0) red[wid] = m;
            __syncthreads();
            float mx = fmaxf(red[half * 2], red[half * 2 + 1]);
            float e = valid ? expf(o - mx) : 0.f;
            float s = e;
#pragma unroll
            for (int off = 16; off; off >>= 1) s += __shfl_xor_sync(0xffffffffu, s, off);
            if (lane == 0) red[4 + wid] = s;
            __syncthreads();
            float tot = red[4 + half * 2] + red[4 + half * 2 + 1];
            if (valid) out[((size_t)seg * NN + n) * DD + d] = o - mx - logf(tot);
            __syncthreads();
        }
    }
}

// ---------------- launch ----------------
extern "C" void kernel_launch(void* const* d_in, const int* in_sizes, int n_in,
                              void* d_out, int out_size) {
    const float* h_states = (const float*)d_in[0];
    const float* W_heads  = (const float*)d_in[1];
    const float* a_heads  = (const float*)d_in[2];
    const float* W_out    = (const float*)d_in[3];
    const float* a_out    = (const float*)d_in[4];
    float* out = (float*)d_out;

    // ---- layer 1 ----
    gemm1_kernel<<<BB * NN / 64, 256>>>(h_states, W_heads, a_heads);
    sort_kernel<<<SEG1, 1024>>>();
    fuse3ab_kernel<<<SEG1, 1024>>>(1);
    qprep_kernel<<<dim3(SEG1, NN / 256), 256>>>();
    combine_kernel<<<dim3(SEG1, CH), 128>>>(1, nullptr);

    // ---- layer 2 ----
    gemm2_kernel<<<BB * NN / 64, 256>>>(W_out, a_out);
    sort_kernel<<<BB, 1024>>>();
    fuse3ab_kernel<<<BB, 1024>>>(2);
    qprep_kernel<<<dim3(BB, NN / 256), 256>>>();
    combine_kernel<<<dim3(BB, CH), 128>>>(2, out);
}

// round 11
// speedup vs baseline: 4.9512x; 4.9512x over previous
#include <cuda_runtime.h>
#include <math.h>

#define NN   2048
#define BB   8
#define HH   4
#define DD   64
#define SEG1 (BB*HH)     // 32 segments in layer 1
#define CH   32          // scan chunks per segment
#define CL   (NN/CH)     // 64 elements per chunk
#define ALPHA_ 0.2f

// ---------------- scratch (static __device__, no allocation) ----------------
__device__ float g_Hbuf [SEG1 * NN * DD];
__device__ float g_H2   [BB   * NN * DD];
__device__ float g_s1   [SEG1 * NN];
__device__ float g_s2   [SEG1 * NN];
__device__ float g_sorted[SEG1 * NN];
__device__ int   g_perm [SEG1 * NN];
__device__ float g_wpre [SEG1 * NN];
__device__ float g_wsuf [SEG1 * NN];
__device__ float g_smax [SEG1];
__device__ float g_CT   [SEG1 * CH * 128];     // chunk offsets (A: 0-63, B: 64-127)
__device__ float g_A1   [SEG1 * (NN+1)];
__device__ float g_B1   [SEG1 * (NN+1)];
__device__ float g_Ah   [SEG1 * (NN+1) * DD];
__device__ float g_Bh   [SEG1 * (NN+1) * DD];
__device__ float g_XC   [BB * NN * HH * DD];
__device__ int   g_qp   [SEG1 * NN];
__device__ float2 g_qr  [SEG1 * NN];

// ---------------- layer-1 GEMM: all 4 heads per block, X tile reused ----------------
__global__ __launch_bounds__(256)
void gemm1_kernel(const float* __restrict__ X,
                  const float* __restrict__ Wmat,
                  const float* __restrict__ avec) {
    __shared__ float XsT[64][68];
    __shared__ float Ws [64][64];
    const int tid = threadIdx.x;
    const int R0  = blockIdx.x * 64;
    const int rq  = tid >> 4;
    const int cq  = tid & 15;

#pragma unroll
    for (int i = 0; i < 16; i++) {
        int idx = tid + i * 256;
        int r = idx >> 6, k = idx & 63;
        XsT[k][r] = X[(size_t)(R0 + r) * 64 + k];
    }

    for (int head = 0; head < HH; head++) {
        __syncthreads();
#pragma unroll
        for (int i = 0; i < 16; i++) {
            int idx = tid + i * 256;
            int k = idx >> 6, d = idx & 63;
            Ws[k][d] = Wmat[((size_t)head * 64 + k) * 64 + d];
        }
        __syncthreads();

        float acc[4][4];
#pragma unroll
        for (int i = 0; i < 4; i++)
#pragma unroll
            for (int j = 0; j < 4; j++) acc[i][j] = 0.f;

#pragma unroll 16
        for (int k = 0; k < 64; k++) {
            float4 xv = *(const float4*)&XsT[k][rq * 4];
            float4 wv = *(const float4*)&Ws [k][cq * 4];
            acc[0][0] += xv.x*wv.x; acc[0][1] += xv.x*wv.y; acc[0][2] += xv.x*wv.z; acc[0][3] += xv.x*wv.w;
            acc[1][0] += xv.y*wv.x; acc[1][1] += xv.y*wv.y; acc[1][2] += xv.y*wv.z; acc[1][3] += xv.y*wv.w;
            acc[2][0] += xv.z*wv.x; acc[2][1] += xv.z*wv.y; acc[2][2] += xv.z*wv.z; acc[2][3] += xv.z*wv.w;
            acc[3][0] += xv.w*wv.x; acc[3][1] += xv.w*wv.y; acc[3][2] += xv.w*wv.z; acc[3][3] += xv.w*wv.w;
        }

        float a1v[4], a2v[4];
#pragma unroll
        for (int j = 0; j < 4; j++) {
            a1v[j] = __ldg(&avec[head * 128 + cq * 4 + j]);
            a2v[j] = __ldg(&avec[head * 128 + 64 + cq * 4 + j]);
        }
#pragma unroll
        for (int i = 0; i < 4; i++) {
            int R = R0 + rq * 4 + i;
            int g = R >> 11;
            int n = R & (NN - 1);
            int seg = g * HH + head;
            size_t base = ((size_t)seg * NN + n) * 64 + cq * 4;
            float4 v; v.x = acc[i][0]; v.y = acc[i][1]; v.z = acc[i][2]; v.w = acc[i][3];
            *(float4*)&g_Hbuf[base] = v;

            float p1 = acc[i][0]*a1v[0] + acc[i][1]*a1v[1] + acc[i][2]*a1v[2] + acc[i][3]*a1v[3];
            float p2 = acc[i][0]*a2v[0] + acc[i][1]*a2v[1] + acc[i][2]*a2v[2] + acc[i][3]*a2v[3];
#pragma unroll
            for (int off = 8; off; off >>= 1) {
                p1 += __shfl_down_sync(0xffffffffu, p1, off, 16);
                p2 += __shfl_down_sync(0xffffffffu, p2, off, 16);
            }
            if (cq == 0) {
                g_s1[seg * NN + n] = p1;
                g_s2[seg * NN + n] = p2;
            }
        }
    }
}

// ---------------- layer-2 GEMM (K = 256) ----------------
__global__ __launch_bounds__(256)
void gemm2_kernel(const float* __restrict__ Wmat,
                  const float* __restrict__ avec) {
    __shared__ float XsT[64][68];
    __shared__ float Ws [64][64];
    const int tid = threadIdx.x;
    const int R0  = blockIdx.x * 64;
    const int rq  = tid >> 4;
    const int cq  = tid & 15;

    float acc[4][4];
#pragma unroll
    for (int i = 0; i < 4; i++)
#pragma unroll
        for (int j = 0; j < 4; j++) acc[i][j] = 0.f;

    for (int kp = 0; kp < 256; kp += 64) {
        __syncthreads();
#pragma unroll
        for (int i = 0; i < 16; i++) {
            int idx = tid + i * 256;
            int r = idx >> 6, k = idx & 63;
            XsT[k][r] = g_XC[(size_t)(R0 + r) * 256 + kp + k];
        }
#pragma unroll
        for (int i = 0; i < 16; i++) {
            int idx = tid + i * 256;
            int k = idx >> 6, d = idx & 63;
            Ws[k][d] = Wmat[((size_t)kp + k) * 64 + d];
        }
        __syncthreads();
#pragma unroll 16
        for (int k = 0; k < 64; k++) {
            float4 xv = *(const float4*)&XsT[k][rq * 4];
            float4 wv = *(const float4*)&Ws [k][cq * 4];
            acc[0][0] += xv.x*wv.x; acc[0][1] += xv.x*wv.y; acc[0][2] += xv.x*wv.z; acc[0][3] += xv.x*wv.w;
            acc[1][0] += xv.y*wv.x; acc[1][1] += xv.y*wv.y; acc[1][2] += xv.y*wv.z; acc[1][3] += xv.y*wv.w;
            acc[2][0] += xv.z*wv.x; acc[2][1] += xv.z*wv.y; acc[2][2] += xv.z*wv.z; acc[2][3] += xv.z*wv.w;
            acc[3][0] += xv.w*wv.x; acc[3][1] += xv.w*wv.y; acc[3][2] += xv.w*wv.z; acc[3][3] += xv.w*wv.w;
        }
    }

    float a1v[4], a2v[4];
#pragma unroll
    for (int j = 0; j < 4; j++) {
        a1v[j] = __ldg(&avec[cq * 4 + j]);
        a2v[j] = __ldg(&avec[64 + cq * 4 + j]);
    }
#pragma unroll
    for (int i = 0; i < 4; i++) {
        int R = R0 + rq * 4 + i;
        int seg = R >> 11;
        int n = R & (NN - 1);
        size_t base = ((size_t)seg * NN + n) * 64 + cq * 4;
        float4 v; v.x = acc[i][0]; v.y = acc[i][1]; v.z = acc[i][2]; v.w = acc[i][3];
        *(float4*)&g_H2[base] = v;

        float p1 = acc[i][0]*a1v[0] + acc[i][1]*a1v[1] + acc[i][2]*a1v[2] + acc[i][3]*a1v[3];
        float p2 = acc[i][0]*a2v[0] + acc[i][1]*a2v[1] + acc[i][2]*a2v[2] + acc[i][3]*a2v[3];
#pragma unroll
        for (int off = 8; off; off >>= 1) {
            p1 += __shfl_down_sync(0xffffffffu, p1, off, 16);
            p2 += __shfl_down_sync(0xffffffffu, p2, off, 16);
        }
        if (cq == 0) {
            g_s1[seg * NN + n] = p1;
            g_s2[seg * NN + n] = p2;
        }
    }
}

// ---------------- bitonic sort: 1024 threads, one comparator each ----------------
__global__ __launch_bounds__(1024)
void sort_kernel() {
    __shared__ float key[NN];
    __shared__ int   idx[NN];
    const int seg = blockIdx.x, tid = threadIdx.x;

    key[tid]        = g_s2[seg * NN + tid];        idx[tid]        = tid;
    key[tid + 1024] = g_s2[seg * NN + tid + 1024]; idx[tid + 1024] = tid + 1024;

    for (int k = 2; k <= NN; k <<= 1) {
        for (int j = k >> 1; j > 0; j >>= 1) {
            __syncthreads();
            int i = ((tid & ~(j - 1)) << 1) | (tid & (j - 1));
            int p = i | j;
            bool up = ((i & k) == 0);
            float ka = key[i], kb = key[p];
            if ((ka > kb) == up) {
                key[i] = kb; key[p] = ka;
                int t = idx[i]; idx[i] = idx[p]; idx[p] = t;
            }
        }
    }
    __syncthreads();

    float smaxv = key[NN - 1];
#pragma unroll
    for (int u = 0; u < 2; u++) {
        int i = tid + u * 1024;
        float kk = key[i];
        g_sorted[seg * NN + i] = kk;
        g_perm  [seg * NN + i] = idx[i];
        g_wsuf  [seg * NN + i] = expf(kk - smaxv);
        g_wpre  [seg * NN + i] = expf(ALPHA_ * (kk - smaxv));
    }
    if (tid == 0) g_smax[seg] = smaxv;
}

// ---------------- fused 3a+3b: chunk sums + all scans, one block per segment ----------------
__global__ __launch_bounds__(1024)
void fuse3ab_kernel(int layer) {
    __shared__ int   sperm[NN];
    __shared__ float sA[NN], sB[NN];
    __shared__ float sCT[CH * 128];
    __shared__ float wtotA[32], wtmpA[32], wtotB[32], wtmpB[32];

    const int seg = blockIdx.x, tid = threadIdx.x;
    const float* __restrict__ H = (layer == 1) ? g_Hbuf : g_H2;

#pragma unroll
    for (int i = 0; i < 2; i++) {
        int idx = tid + i * 1024;
        sperm[idx] = g_perm[seg * NN + idx];
        sA[idx]    = g_wpre[seg * NN + idx];
        sB[idx]    = g_wsuf[seg * NN + idx];
    }
    __syncthreads();

    // chunk sums: 2048 (chunk,d) tasks, 2 per thread
    const size_t segNN = (size_t)seg * NN;
#pragma unroll
    for (int rep = 0; rep < 2; rep++) {
        int task = tid + rep * 1024;
        int c = task >> 6, d = task & 63;
        int qb = c * CL;
        float accA = 0.f, accB = 0.f;
#pragma unroll 8
        for (int q = 0; q < CL; q++) {
            float h = __ldg(&H[(segNN + sperm[qb + q]) * 64 + d]);
            accA += sA[qb + q] * h;
            accB += sB[qb + q] * h;
        }
        sCT[c * 128 + d]      = accA;
        sCT[c * 128 + 64 + d] = accB;
    }
    __syncthreads();

    // chunk offset scans -> g_CT; boundary rows of g_Ah / g_Bh at p == NN
    if (tid < 64) {
        int d = tid; float run = 0.f;
        for (int c = 0; c < CH; c++) {
            float t = sCT[c * 128 + d];
            g_CT[(seg * CH + c) * 128 + d] = run; run += t;
        }
        g_Ah[((size_t)seg * (NN + 1) + NN) * 64 + d] = run;   // full prefix total
    } else if (tid < 128) {
        int d = tid - 64; float run = 0.f;
        for (int c = CH - 1; c >= 0; c--) {
            float t = sCT[c * 128 + 64 + d];
            g_CT[(seg * CH + c) * 128 + 64 + d] = run; run += t;
        }
        g_Bh[((size_t)seg * (NN + 1) + NN) * 64 + d] = 0.f;   // empty suffix
    }

    // scalar scans: A1 = exclusive prefix of wpre, B1 = inclusive suffix of wsuf
    const int j0 = tid * 2;
    const int lane = tid & 31, wid = tid >> 5;
    float wa0 = sA[j0], wa1 = sA[j0 + 1];
    float wb0 = sB[j0], wb1 = sB[j0 + 1];
    float saT = wa0 + wa1;
    float sbT = wb0 + wb1;

    float xa = saT;
#pragma unroll
    for (int off = 1; off < 32; off <<= 1) {
        float y = __shfl_up_sync(0xffffffffu, xa, off);
        if (lane >= off) xa += y;
    }
    float exA = xa - saT;
    float xb = sbT;
#pragma unroll
    for (int off = 1; off < 32; off <<= 1) {
        float y = __shfl_down_sync(0xffffffffu, xb, off);
        if (lane < 32 - off) xb += y;
    }
    float exB = xb - sbT;

    if (lane == 31) wtotA[wid] = xa;
    if (lane == 0)  wtotB[wid] = xb;
    __syncthreads();
    if (tid == 0) {
        float r = 0.f;
        for (int w = 0; w < 32; w++) { float t = wtotA[w]; wtmpA[w] = r; r += t; }
        g_A1[seg * (NN + 1) + NN] = r;
        r = 0.f;
        for (int w = 31; w >= 0; w--) { float t = wtotB[w]; wtmpB[w] = r; r += t; }
        g_B1[seg * (NN + 1) + NN] = 0.f;
    }
    __syncthreads();
    float oa = wtmpA[wid] + exA;
    float ob = wtmpB[wid] + exB;
    g_A1[seg * (NN + 1) + j0]     = oa;
    g_A1[seg * (NN + 1) + j0 + 1] = oa + wa0;
    g_B1[seg * (NN + 1) + j0]     = ob + wb0 + wb1;
    g_B1[seg * (NN + 1) + j0 + 1] = ob + wb1;
}

// ---------------- pass 3c: smem-staged tile, both scan directions ----------------
__global__ __launch_bounds__(128)
void pass3c_kernel(int layer) {
    const int seg = blockIdx.x, c = blockIdx.y, tid = threadIdx.x;
    const float* __restrict__ Hmat = (layer == 1) ? g_Hbuf : g_H2;
    const int q0 = c * CL;

    __shared__ int   sp[CL];
    __shared__ float swA[CL], swB[CL];
    __shared__ float tile[CL * 64];     // tile[q*64 + d]

    if (tid < 64) {
        sp [tid] = g_perm[seg * NN + q0 + tid];
        swA[tid] = g_wpre[seg * NN + q0 + tid];
    } else {
        swB[tid - 64] = g_wsuf[seg * NN + q0 + tid - 64];
    }
    __syncthreads();

    const size_t segNN = (size_t)seg * NN;
#pragma unroll
    for (int i = 0; i < 32; i++) {
        int lin = tid + 128 * i;
        int q = lin >> 6, d = lin & 63;
        tile[lin] = __ldg(&Hmat[(segNN + sp[q]) * 64 + d]);
    }
    __syncthreads();

    const int d = tid & 63;
    const size_t rowbase = ((size_t)seg * (NN + 1) + q0) * 64 + d;
    float run = g_CT[(seg * CH + c) * 128 + tid];

    if (tid < 64) {  // forward exclusive prefix of wpre*h
#pragma unroll 8
        for (int t = 0; t < CL; t++) {
            g_Ah[rowbase + (size_t)t * 64] = run;
            run += swA[t] * tile[t * 64 + d];
        }
    } else {         // reverse inclusive suffix of wsuf*h
#pragma unroll 8
        for (int t = CL - 1; t >= 0; t--) {
            run += swB[t] * tile[t * 64 + d];
            g_Bh[rowbase + (size_t)t * 64] = run;
        }
    }
}

// ---------------- qprep: one binary search + factor precompute per query ----------------
__global__ __launch_bounds__(256)
void qprep_kernel() {
    const int seg = blockIdx.x, tid = threadIdx.x;
    const int n = blockIdx.y * 256 + tid;

    __shared__ float srt[NN];
#pragma unroll
    for (int i = 0; i < 8; i++) srt[tid + 256 * i] = g_sorted[seg * NN + tid + 256 * i];
    __syncthreads();

    float s1v  = g_s1[seg * NN + n];
    float smax = g_smax[seg];
    float u = s1v + smax;
    float m = (u >= 0.f) ? u : ALPHA_ * u;
    float f1 = expf(u - m);
    float f2 = expf(ALPHA_ * u - m);
    float tau = -s1v;
    int lo = 0, hi = NN;
    while (lo < hi) {
        int mid = (lo + hi) >> 1;
        if (srt[mid] < tau) lo = mid + 1; else hi = mid;
    }
    int p = lo;
    float A1v = __ldg(&g_A1[seg * (NN + 1) + p]);
    float B1v = __ldg(&g_B1[seg * (NN + 1) + p]);
    float den = f1 * B1v + f2 * A1v;
    g_qp[seg * NN + n] = p;
    g_qr[seg * NN + n] = make_float2(f2 / den, f1 / den);
}

// ---------------- layer-1 combine: pure stream, elu -> XC ----------------
__global__ __launch_bounds__(256)
void combine1_kernel() {
    const int seg = blockIdx.y, tid = threadIdx.x;
    const int n  = blockIdx.x * 16 + (tid >> 4);
    const int d4 = (tid & 15) * 4;

    int    p = g_qp[seg * NN + n];
    float2 r = g_qr[seg * NN + n];
    size_t rb = ((size_t)seg * (NN + 1) + p) * 64 + d4;
    float4 a = *(const float4*)&g_Ah[rb];
    float4 b = *(const float4*)&g_Bh[rb];
    float4 o;
    o.x = r.y * b.x + r.x * a.x;
    o.y = r.y * b.y + r.x * a.y;
    o.z = r.y * b.z + r.x * a.z;
    o.w = r.y * b.w + r.x * a.w;
    o.x = (o.x > 0.f) ? o.x : expm1f(o.x);
    o.y = (o.y > 0.f) ? o.y : expm1f(o.y);
    o.z = (o.z > 0.f) ? o.z : expm1f(o.z);
    o.w = (o.w > 0.f) ? o.w : expm1f(o.w);

    int g = seg >> 2, h = seg & 3;
    *(float4*)&g_XC[((size_t)g * NN + n) * (HH * DD) + h * DD + d4] = o;
}

// ---------------- layer-2 combine: stream, elu -> log_softmax -> out ----------------
__global__ __launch_bounds__(256)
void combine2_kernel(float* __restrict__ out) {
    const int seg = blockIdx.y, tid = threadIdx.x;
    const int n  = blockIdx.x * 16 + (tid >> 4);
    const int d4 = (tid & 15) * 4;

    int    p = g_qp[seg * NN + n];
    float2 r = g_qr[seg * NN + n];
    size_t rb = ((size_t)seg * (NN + 1) + p) * 64 + d4;
    float4 a = *(const float4*)&g_Ah[rb];
    float4 b = *(const float4*)&g_Bh[rb];
    float4 o;
    o.x = r.y * b.x + r.x * a.x;
    o.y = r.y * b.y + r.x * a.y;
    o.z = r.y * b.z + r.x * a.z;
    o.w = r.y * b.w + r.x * a.w;
    o.x = (o.x > 0.f) ? o.x : expm1f(o.x);
    o.y = (o.y > 0.f) ? o.y : expm1f(o.y);
    o.z = (o.z > 0.f) ? o.z : expm1f(o.z);
    o.w = (o.w > 0.f) ? o.w : expm1f(o.w);

    // log_softmax over 64 dims: 16 lanes per row, 4 elems per lane
    float lm = fmaxf(fmaxf(o.x, o.y), fmaxf(o.z, o.w));
#pragma unroll
    for (int off = 8; off; off >>= 1)
        lm = fmaxf(lm, __shfl_xor_sync(0xffffffffu, lm, off, 16));
    float ls = expf(o.x - lm) + expf(o.y - lm) + expf(o.z - lm) + expf(o.w - lm);
#pragma unroll
    for (int off = 8; off; off >>= 1)
        ls += __shfl_xor_sync(0xffffffffu, ls, off, 16);
    float sub = lm + logf(ls);

    float4 w;
    w.x = o.x - sub; w.y = o.y - sub; w.z = o.z - sub; w.w = o.w - sub;
    *(float4*)&out[((size_t)seg * NN + n) * DD + d4] = w;
}

// ---------------- launch ----------------
extern "C" void kernel_launch(void* const* d_in, const int* in_sizes, int n_in,
                              void* d_out, int out_size) {
    const float* h_states = (const float*)d_in[0];
    const float* W_heads  = (const float*)d_in[1];
    const float* a_heads  = (const float*)d_in[2];
    const float* W_out    = (const float*)d_in[3];
    const float* a_out    = (const float*)d_in[4];
    float* out = (float*)d_out;

    // ---- layer 1 ----
    gemm1_kernel<<<BB * NN / 64, 256>>>(h_states, W_heads, a_heads);
    sort_kernel<<<SEG1, 1024>>>();
    fuse3ab_kernel<<<SEG1, 1024>>>(1);
    pass3c_kernel<<<dim3(SEG1, CH), 128>>>(1);
    qprep_kernel<<<dim3(SEG1, NN / 256), 256>>>();
    combine1_kernel<<<dim3(NN / 16, SEG1), 256>>>();

    // ---- layer 2 ----
    gemm2_kernel<<<BB * NN / 64, 256>>>(W_out, a_out);
    sort_kernel<<<BB, 1024>>>();
    fuse3ab_kernel<<<BB, 1024>>>(2);
    pass3c_kernel<<<dim3(BB, CH), 128>>>(2);
    qprep_kernel<<<dim3(BB, NN / 256), 256>>>();
    combine2_kernel<<<dim3(NN / 16, BB), 256>>>(out);
}

// round 12
// speedup vs baseline: 5.5312x; 1.1171x over previous
#include <cuda_runtime.h>
#include <math.h>

#define NN   2048
#define BB   8
#define HH   4
#define DD   64
#define SEG1 (BB*HH)     // 32 segments in layer 1
#define CH   32          // scan chunks per segment
#define CL   (NN/CH)     // 64 elements per chunk
#define NCPB 2           // chunks per pass3c block
#define ALPHA_ 0.2f

// ---------------- scratch (static __device__, no allocation) ----------------
__device__ float g_Hbuf [SEG1 * NN * DD];
__device__ float g_H2   [BB   * NN * DD];
__device__ float g_s1   [SEG1 * NN];
__device__ float g_s2   [SEG1 * NN];
__device__ float g_sorted[SEG1 * NN];
__device__ int   g_perm [SEG1 * NN];
__device__ float g_wpre [SEG1 * NN];
__device__ float g_wsuf [SEG1 * NN];
__device__ float g_smax [SEG1];
__device__ float g_CT   [SEG1 * CH * 128];
__device__ float g_A1   [SEG1 * (NN+1)];
__device__ float g_B1   [SEG1 * (NN+1)];
__device__ float g_Ah   [SEG1 * (NN+1) * DD];
__device__ float g_Bh   [SEG1 * (NN+1) * DD];
__device__ float g_XC   [BB * NN * HH * DD];
__device__ int   g_qp   [SEG1 * NN];
__device__ float2 g_qr  [SEG1 * NN];

// ---------------- layer-1 GEMM: all 4 heads per block, X tile reused ----------------
__global__ __launch_bounds__(256)
void gemm1_kernel(const float* __restrict__ X,
                  const float* __restrict__ Wmat,
                  const float* __restrict__ avec) {
    __shared__ float XsT[64][68];
    __shared__ float Ws [64][64];
    const int tid = threadIdx.x;
    const int R0  = blockIdx.x * 64;
    const int rq  = tid >> 4;
    const int cq  = tid & 15;

#pragma unroll
    for (int i = 0; i < 16; i++) {
        int idx = tid + i * 256;
        int r = idx >> 6, k = idx & 63;
        XsT[k][r] = X[(size_t)(R0 + r) * 64 + k];
    }

    for (int head = 0; head < HH; head++) {
        __syncthreads();
#pragma unroll
        for (int i = 0; i < 16; i++) {
            int idx = tid + i * 256;
            int k = idx >> 6, d = idx & 63;
            Ws[k][d] = Wmat[((size_t)head * 64 + k) * 64 + d];
        }
        __syncthreads();

        float acc[4][4];
#pragma unroll
        for (int i = 0; i < 4; i++)
#pragma unroll
            for (int j = 0; j < 4; j++) acc[i][j] = 0.f;

#pragma unroll 16
        for (int k = 0; k < 64; k++) {
            float4 xv = *(const float4*)&XsT[k][rq * 4];
            float4 wv = *(const float4*)&Ws [k][cq * 4];
            acc[0][0] += xv.x*wv.x; acc[0][1] += xv.x*wv.y; acc[0][2] += xv.x*wv.z; acc[0][3] += xv.x*wv.w;
            acc[1][0] += xv.y*wv.x; acc[1][1] += xv.y*wv.y; acc[1][2] += xv.y*wv.z; acc[1][3] += xv.y*wv.w;
            acc[2][0] += xv.z*wv.x; acc[2][1] += xv.z*wv.y; acc[2][2] += xv.z*wv.z; acc[2][3] += xv.z*wv.w;
            acc[3][0] += xv.w*wv.x; acc[3][1] += xv.w*wv.y; acc[3][2] += xv.w*wv.z; acc[3][3] += xv.w*wv.w;
        }

        float a1v[4], a2v[4];
#pragma unroll
        for (int j = 0; j < 4; j++) {
            a1v[j] = __ldg(&avec[head * 128 + cq * 4 + j]);
            a2v[j] = __ldg(&avec[head * 128 + 64 + cq * 4 + j]);
        }
#pragma unroll
        for (int i = 0; i < 4; i++) {
            int R = R0 + rq * 4 + i;
            int g = R >> 11;
            int n = R & (NN - 1);
            int seg = g * HH + head;
            size_t base = ((size_t)seg * NN + n) * 64 + cq * 4;
            float4 v; v.x = acc[i][0]; v.y = acc[i][1]; v.z = acc[i][2]; v.w = acc[i][3];
            *(float4*)&g_Hbuf[base] = v;

            float p1 = acc[i][0]*a1v[0] + acc[i][1]*a1v[1] + acc[i][2]*a1v[2] + acc[i][3]*a1v[3];
            float p2 = acc[i][0]*a2v[0] + acc[i][1]*a2v[1] + acc[i][2]*a2v[2] + acc[i][3]*a2v[3];
#pragma unroll
            for (int off = 8; off; off >>= 1) {
                p1 += __shfl_down_sync(0xffffffffu, p1, off, 16);
                p2 += __shfl_down_sync(0xffffffffu, p2, off, 16);
            }
            if (cq == 0) {
                g_s1[seg * NN + n] = p1;
                g_s2[seg * NN + n] = p2;
            }
        }
    }
}

// ---------------- layer-2 GEMM (K = 256) ----------------
__global__ __launch_bounds__(256)
void gemm2_kernel(const float* __restrict__ Wmat,
                  const float* __restrict__ avec) {
    __shared__ float XsT[64][68];
    __shared__ float Ws [64][64];
    const int tid = threadIdx.x;
    const int R0  = blockIdx.x * 64;
    const int rq  = tid >> 4;
    const int cq  = tid & 15;

    float acc[4][4];
#pragma unroll
    for (int i = 0; i < 4; i++)
#pragma unroll
        for (int j = 0; j < 4; j++) acc[i][j] = 0.f;

    for (int kp = 0; kp < 256; kp += 64) {
        __syncthreads();
#pragma unroll
        for (int i = 0; i < 16; i++) {
            int idx = tid + i * 256;
            int r = idx >> 6, k = idx & 63;
            XsT[k][r] = g_XC[(size_t)(R0 + r) * 256 + kp + k];
        }
#pragma unroll
        for (int i = 0; i < 16; i++) {
            int idx = tid + i * 256;
            int k = idx >> 6, d = idx & 63;
            Ws[k][d] = Wmat[((size_t)kp + k) * 64 + d];
        }
        __syncthreads();
#pragma unroll 16
        for (int k = 0; k < 64; k++) {
            float4 xv = *(const float4*)&XsT[k][rq * 4];
            float4 wv = *(const float4*)&Ws [k][cq * 4];
            acc[0][0] += xv.x*wv.x; acc[0][1] += xv.x*wv.y; acc[0][2] += xv.x*wv.z; acc[0][3] += xv.x*wv.w;
            acc[1][0] += xv.y*wv.x; acc[1][1] += xv.y*wv.y; acc[1][2] += xv.y*wv.z; acc[1][3] += xv.y*wv.w;
            acc[2][0] += xv.z*wv.x; acc[2][1] += xv.z*wv.y; acc[2][2] += xv.z*wv.z; acc[2][3] += xv.z*wv.w;
            acc[3][0] += xv.w*wv.x; acc[3][1] += xv.w*wv.y; acc[3][2] += xv.w*wv.z; acc[3][3] += xv.w*wv.w;
        }
    }

    float a1v[4], a2v[4];
#pragma unroll
    for (int j = 0; j < 4; j++) {
        a1v[j] = __ldg(&avec[cq * 4 + j]);
        a2v[j] = __ldg(&avec[64 + cq * 4 + j]);
    }
#pragma unroll
    for (int i = 0; i < 4; i++) {
        int R = R0 + rq * 4 + i;
        int seg = R >> 11;
        int n = R & (NN - 1);
        size_t base = ((size_t)seg * NN + n) * 64 + cq * 4;
        float4 v; v.x = acc[i][0]; v.y = acc[i][1]; v.z = acc[i][2]; v.w = acc[i][3];
        *(float4*)&g_H2[base] = v;

        float p1 = acc[i][0]*a1v[0] + acc[i][1]*a1v[1] + acc[i][2]*a1v[2] + acc[i][3]*a1v[3];
        float p2 = acc[i][0]*a2v[0] + acc[i][1]*a2v[1] + acc[i][2]*a2v[2] + acc[i][3]*a2v[3];
#pragma unroll
        for (int off = 8; off; off >>= 1) {
            p1 += __shfl_down_sync(0xffffffffu, p1, off, 16);
            p2 += __shfl_down_sync(0xffffffffu, p2, off, 16);
        }
        if (cq == 0) {
            g_s1[seg * NN + n] = p1;
            g_s2[seg * NN + n] = p2;
        }
    }
}

// ---------------- bitonic sort: 1024 threads, one comparator each ----------------
__global__ __launch_bounds__(1024)
void sort_kernel() {
    __shared__ float key[NN];
    __shared__ int   idx[NN];
    const int seg = blockIdx.x, tid = threadIdx.x;

    key[tid]        = g_s2[seg * NN + tid];        idx[tid]        = tid;
    key[tid + 1024] = g_s2[seg * NN + tid + 1024]; idx[tid + 1024] = tid + 1024;

    for (int k = 2; k <= NN; k <<= 1) {
        for (int j = k >> 1; j > 0; j >>= 1) {
            __syncthreads();
            int i = ((tid & ~(j - 1)) << 1) | (tid & (j - 1));
            int p = i | j;
            bool up = ((i & k) == 0);
            float ka = key[i], kb = key[p];
            if ((ka > kb) == up) {
                key[i] = kb; key[p] = ka;
                int t = idx[i]; idx[i] = idx[p]; idx[p] = t;
            }
        }
    }
    __syncthreads();

    float smaxv = key[NN - 1];
#pragma unroll
    for (int u = 0; u < 2; u++) {
        int i = tid + u * 1024;
        float kk = key[i];
        g_sorted[seg * NN + i] = kk;
        g_perm  [seg * NN + i] = idx[i];
        g_wsuf  [seg * NN + i] = expf(kk - smaxv);
        g_wpre  [seg * NN + i] = expf(ALPHA_ * (kk - smaxv));
    }
    if (tid == 0) g_smax[seg] = smaxv;
}

// ---------------- pass 3a: per-chunk sums, BOTH halves per thread (one H load) ----------------
__global__ __launch_bounds__(64)
void pass3a_kernel(int layer) {
    const int seg = blockIdx.x, c = blockIdx.y, d = threadIdx.x;
    const float* __restrict__ Hmat = (layer == 1) ? g_Hbuf : g_H2;
    const int q0 = c * CL;

    __shared__ int   sp[CL];
    __shared__ float swA[CL], swB[CL];
    sp [d] = g_perm[seg * NN + q0 + d];
    swA[d] = g_wpre[seg * NN + q0 + d];
    swB[d] = g_wsuf[seg * NN + q0 + d];
    __syncthreads();

    const size_t segNN = (size_t)seg * NN;
    float accA = 0.f, accB = 0.f;
#pragma unroll 8
    for (int q = 0; q < CL; q++) {
        float h = __ldg(&Hmat[(segNN + sp[q]) * 64 + d]);
        accA += swA[q] * h;
        accB += swB[q] * h;
    }
    g_CT[(seg * CH + c) * 128 + d]      = accA;
    g_CT[(seg * CH + c) * 128 + 64 + d] = accB;
}

// ---------------- pass 3b: chunk-offset scan + scalar scans ----------------
__global__ __launch_bounds__(256)
void pass3b_kernel() {
    const int seg = blockIdx.x, tid = threadIdx.x;
    const int lane = tid & 31, wid = tid >> 5;
    __shared__ float wsumA[8], wsumB[8], woffA[8], woffB[8];

    if (tid < 128) {
        float v[CH];
#pragma unroll
        for (int c = 0; c < CH; c++) v[c] = g_CT[(seg * CH + c) * 128 + tid];
        if (tid < 64) {
            float run = 0.f;
#pragma unroll
            for (int c = 0; c < CH; c++) { float t = v[c]; g_CT[(seg * CH + c) * 128 + tid] = run; run += t; }
            g_Ah[((size_t)seg * (NN + 1) + NN) * 64 + tid] = run;
        } else {
            float run = 0.f;
#pragma unroll
            for (int c = CH - 1; c >= 0; c--) { float t = v[c]; g_CT[(seg * CH + c) * 128 + tid] = run; run += t; }
            g_Bh[((size_t)seg * (NN + 1) + NN) * 64 + (tid - 64)] = 0.f;
        }
    }

    const int qb = tid * 8;
    float wa[8], wb[8];
    {
        float4 t0 = *(const float4*)&g_wpre[seg * NN + qb];
        float4 t1 = *(const float4*)&g_wpre[seg * NN + qb + 4];
        wa[0]=t0.x; wa[1]=t0.y; wa[2]=t0.z; wa[3]=t0.w;
        wa[4]=t1.x; wa[5]=t1.y; wa[6]=t1.z; wa[7]=t1.w;
        float4 u0 = *(const float4*)&g_wsuf[seg * NN + qb];
        float4 u1 = *(const float4*)&g_wsuf[seg * NN + qb + 4];
        wb[0]=u0.x; wb[1]=u0.y; wb[2]=u0.z; wb[3]=u0.w;
        wb[4]=u1.x; wb[5]=u1.y; wb[6]=u1.z; wb[7]=u1.w;
    }
    float la[8], lb[8];
    float sa = 0.f;
#pragma unroll
    for (int i = 0; i < 8; i++) { la[i] = sa; sa += wa[i]; }
    float sb = 0.f;
#pragma unroll
    for (int i = 7; i >= 0; i--) { sb += wb[i]; lb[i] = sb; }

    float xa = sa;
#pragma unroll
    for (int off = 1; off < 32; off <<= 1) {
        float y = __shfl_up_sync(0xffffffffu, xa, off);
        if (lane >= off) xa += y;
    }
    float exA = xa - sa;
    float xb = sb;
#pragma unroll
    for (int off = 1; off < 32; off <<= 1) {
        float y = __shfl_down_sync(0xffffffffu, xb, off);
        if (lane < 32 - off) xb += y;
    }
    float exB = xb - sb;

    if (lane == 31) wsumA[wid] = xa;
    if (lane == 0)  wsumB[wid] = xb;
    __syncthreads();
    if (tid == 0) {
        float r = 0.f;
        for (int w = 0; w < 8; w++) { float t = wsumA[w]; woffA[w] = r; r += t; }
        g_A1[seg * (NN + 1) + NN] = r;
        r = 0.f;
        for (int w = 7; w >= 0; w--) { float t = wsumB[w]; woffB[w] = r; r += t; }
        g_B1[seg * (NN + 1) + NN] = 0.f;
    }
    __syncthreads();
    float oa = woffA[wid] + exA, ob = woffB[wid] + exB;
#pragma unroll
    for (int i = 0; i < 8; i++) {
        g_A1[seg * (NN + 1) + qb + i] = oa + la[i];
        g_B1[seg * (NN + 1) + qb + i] = ob + lb[i];
    }
}

// ---------------- pass 3c: 2 chunks/block, float2 scan lanes ----------------
__global__ __launch_bounds__(128)
void pass3c_kernel(int layer) {
    const int seg = blockIdx.x, cb = blockIdx.y * NCPB, tid = threadIdx.x;
    const float* __restrict__ Hmat = (layer == 1) ? g_Hbuf : g_H2;

    __shared__ int   sp [NCPB * CL];
    __shared__ float swA[NCPB * CL], swB[NCPB * CL];
    __shared__ float tile[NCPB * CL * 64];   // 32KB

    // stage perm + weights (NCPB*CL == 128 == blockDim)
    sp [tid] = g_perm[seg * NN + cb * CL + tid];
    swA[tid] = g_wpre[seg * NN + cb * CL + tid];
    swB[tid] = g_wsuf[seg * NN + cb * CL + tid];
    __syncthreads();

    // stage tile: 128 rows x 16 float4, 8 rows in flight
    const size_t segNN = (size_t)seg * NN;
    {
        int rg = tid >> 4;        // 0..7
        int cq = tid & 15;        // float4 slot
#pragma unroll
        for (int rr = 0; rr < NCPB * CL; rr += 8) {
            int r = rr + rg;
            const float4* src = (const float4*)&Hmat[(segNN + sp[r]) * 64];
            ((float4*)&tile[r * 64])[cq] = __ldg(&src[cq]);
        }
    }
    __syncthreads();

    const int ci   = tid >> 6;           // chunk within block
    const int half = (tid >> 5) & 1;     // 0 = A (forward), 1 = B (backward)
    const int d2   = (tid & 31) * 2;
    const int c    = cb + ci;
    const float* tl = &tile[ci * CL * 64];
    const float* w  = half ? &swB[ci * CL] : &swA[ci * CL];
    const size_t rowbase = ((size_t)seg * (NN + 1) + c * CL) * 64 + d2;

    float2 run = *(const float2*)&g_CT[(seg * CH + c) * 128 + half * 64 + d2];

    if (half == 0) {   // forward exclusive prefix of wpre*h
#pragma unroll 8
        for (int t = 0; t < CL; t++) {
            *(float2*)&g_Ah[rowbase + (size_t)t * 64] = run;
            float2 h = *(const float2*)&tl[t * 64 + d2];
            run.x += w[t] * h.x;
            run.y += w[t] * h.y;
        }
    } else {           // reverse inclusive suffix of wsuf*h
#pragma unroll 8
        for (int t = CL - 1; t >= 0; t--) {
            float2 h = *(const float2*)&tl[t * 64 + d2];
            run.x += w[t] * h.x;
            run.y += w[t] * h.y;
            *(float2*)&g_Bh[rowbase + (size_t)t * 64] = run;
        }
    }
}

// ---------------- qprep: one binary search + factor precompute per query ----------------
__global__ __launch_bounds__(256)
void qprep_kernel() {
    const int seg = blockIdx.x, tid = threadIdx.x;
    const int n = blockIdx.y * 256 + tid;

    __shared__ float srt[NN];
#pragma unroll
    for (int i = 0; i < 8; i++) srt[tid + 256 * i] = g_sorted[seg * NN + tid + 256 * i];
    __syncthreads();

    float s1v  = g_s1[seg * NN + n];
    float smax = g_smax[seg];
    float u = s1v + smax;
    float m = (u >= 0.f) ? u : ALPHA_ * u;
    float f1 = expf(u - m);
    float f2 = expf(ALPHA_ * u - m);
    float tau = -s1v;
    int lo = 0, hi = NN;
    while (lo < hi) {
        int mid = (lo + hi) >> 1;
        if (srt[mid] < tau) lo = mid + 1; else hi = mid;
    }
    int p = lo;
    float A1v = __ldg(&g_A1[seg * (NN + 1) + p]);
    float B1v = __ldg(&g_B1[seg * (NN + 1) + p]);
    float den = f1 * B1v + f2 * A1v;
    g_qp[seg * NN + n] = p;
    g_qr[seg * NN + n] = make_float2(f2 / den, f1 / den);
}

// ---------------- layer-1 combine: pure stream, elu -> XC ----------------
__global__ __launch_bounds__(256)
void combine1_kernel() {
    const int seg = blockIdx.y, tid = threadIdx.x;
    const int n  = blockIdx.x * 16 + (tid >> 4);
    const int d4 = (tid & 15) * 4;

    int    p = g_qp[seg * NN + n];
    float2 r = g_qr[seg * NN + n];
    size_t rb = ((size_t)seg * (NN + 1) + p) * 64 + d4;
    float4 a = *(const float4*)&g_Ah[rb];
    float4 b = *(const float4*)&g_Bh[rb];
    float4 o;
    o.x = r.y * b.x + r.x * a.x;
    o.y = r.y * b.y + r.x * a.y;
    o.z = r.y * b.z + r.x * a.z;
    o.w = r.y * b.w + r.x * a.w;
    o.x = (o.x > 0.f) ? o.x : expm1f(o.x);
    o.y = (o.y > 0.f) ? o.y : expm1f(o.y);
    o.z = (o.z > 0.f) ? o.z : expm1f(o.z);
    o.w = (o.w > 0.f) ? o.w : expm1f(o.w);

    int g = seg >> 2, h = seg & 3;
    *(float4*)&g_XC[((size_t)g * NN + n) * (HH * DD) + h * DD + d4] = o;
}

// ---------------- layer-2 combine: stream, elu -> log_softmax -> out ----------------
__global__ __launch_bounds__(256)
void combine2_kernel(float* __restrict__ out) {
    const int seg = blockIdx.y, tid = threadIdx.x;
    const int n  = blockIdx.x * 16 + (tid >> 4);
    const int d4 = (tid & 15) * 4;

    int    p = g_qp[seg * NN + n];
    float2 r = g_qr[seg * NN + n];
    size_t rb = ((size_t)seg * (NN + 1) + p) * 64 + d4;
    float4 a = *(const float4*)&g_Ah[rb];
    float4 b = *(const float4*)&g_Bh[rb];
    float4 o;
    o.x = r.y * b.x + r.x * a.x;
    o.y = r.y * b.y + r.x * a.y;
    o.z = r.y * b.z + r.x * a.z;
    o.w = r.y * b.w + r.x * a.w;
    o.x = (o.x > 0.f) ? o.x : expm1f(o.x);
    o.y = (o.y > 0.f) ? o.y : expm1f(o.y);
    o.z = (o.z > 0.f) ? o.z : expm1f(o.z);
    o.w = (o.w > 0.f) ? o.w : expm1f(o.w);

    float lm = fmaxf(fmaxf(o.x, o.y), fmaxf(o.z, o.w));
#pragma unroll
    for (int off = 8; off; off >>= 1)
        lm = fmaxf(lm, __shfl_xor_sync(0xffffffffu, lm, off, 16));
    float ls = expf(o.x - lm) + expf(o.y - lm) + expf(o.z - lm) + expf(o.w - lm);
#pragma unroll
    for (int off = 8; off; off >>= 1)
        ls += __shfl_xor_sync(0xffffffffu, ls, off, 16);
    float sub = lm + logf(ls);

    float4 w;
    w.x = o.x - sub; w.y = o.y - sub; w.z = o.z - sub; w.w = o.w - sub;
    *(float4*)&out[((size_t)seg * NN + n) * DD + d4] = w;
}

// ---------------- launch ----------------
extern "C" void kernel_launch(void* const* d_in, const int* in_sizes, int n_in,
                              void* d_out, int out_size) {
    const float* h_states = (const float*)d_in[0];
    const float* W_heads  = (const float*)d_in[1];
    const float* a_heads  = (const float*)d_in[2];
    const float* W_out    = (const float*)d_in[3];
    const float* a_out    = (const float*)d_in[4];
    float* out = (float*)d_out;

    // ---- layer 1 ----
    gemm1_kernel<<<BB * NN / 64, 256>>>(h_states, W_heads, a_heads);
    sort_kernel<<<SEG1, 1024>>>();
    pass3a_kernel<<<dim3(SEG1, CH), 64>>>(1);
    pass3b_kernel<<<SEG1, 256>>>();
    pass3c_kernel<<<dim3(SEG1, CH / NCPB), 128>>>(1);
    qprep_kernel<<<dim3(SEG1, NN / 256), 256>>>();
    combine1_kernel<<<dim3(NN / 16, SEG1), 256>>>();

    // ---- layer 2 ----
    gemm2_kernel<<<BB * NN / 64, 256>>>(W_out, a_out);
    sort_kernel<<<BB, 1024>>>();
    pass3a_kernel<<<dim3(BB, CH), 64>>>(2);
    pass3b_kernel<<<BB, 256>>>();
    pass3c_kernel<<<dim3(BB, CH / NCPB), 128>>>(2);
    qprep_kernel<<<dim3(BB, NN / 256), 256>>>();
    combine2_kernel<<<dim3(NN / 16, BB), 256>>>(out);
}

// round 13
// speedup vs baseline: 5.6162x; 1.0154x over previous
#include <cuda_runtime.h>
#include <math.h>

#define NN   2048
#define BB   8
#define HH   4
#define DD   64
#define SEG1 (BB*HH)     // 32 segments in layer 1
#define CH   32          // scan chunks per segment
#define CL   (NN/CH)     // 64 elements per chunk
#define NCPB 2           // chunks per pass3c block
#define ALPHA_ 0.2f

// ---------------- scratch (static __device__, no allocation) ----------------
__device__ float g_Hbuf [SEG1 * NN * DD];
__device__ float g_H2   [BB   * NN * DD];
__device__ float g_s1   [SEG1 * NN];
__device__ float g_s2   [SEG1 * NN];
__device__ float g_sorted[SEG1 * NN];
__device__ int   g_perm [SEG1 * NN];
__device__ float g_wpre [SEG1 * NN];
__device__ float g_wsuf [SEG1 * NN];
__device__ float g_smax [SEG1];
__device__ float g_CT   [SEG1 * CH * 128];     // raw chunk totals (A: 0-63, B: 64-127)
__device__ float g_Ah   [SEG1 * (NN+1) * DD];
__device__ float g_Bh   [SEG1 * (NN+1) * DD];
__device__ float g_XC   [BB * NN * HH * DD];
__device__ int   g_qp   [SEG1 * NN];
__device__ float2 g_qr  [SEG1 * NN];

// ---------------- layer-1 GEMM: all 4 heads per block, X tile reused ----------------
__global__ __launch_bounds__(256)
void gemm1_kernel(const float* __restrict__ X,
                  const float* __restrict__ Wmat,
                  const float* __restrict__ avec) {
    __shared__ float XsT[64][68];
    __shared__ float Ws [64][64];
    const int tid = threadIdx.x;
    const int R0  = blockIdx.x * 64;
    const int rq  = tid >> 4;
    const int cq  = tid & 15;

#pragma unroll
    for (int i = 0; i < 16; i++) {
        int idx = tid + i * 256;
        int r = idx >> 6, k = idx & 63;
        XsT[k][r] = X[(size_t)(R0 + r) * 64 + k];
    }

    for (int head = 0; head < HH; head++) {
        __syncthreads();
#pragma unroll
        for (int i = 0; i < 16; i++) {
            int idx = tid + i * 256;
            int k = idx >> 6, d = idx & 63;
            Ws[k][d] = Wmat[((size_t)head * 64 + k) * 64 + d];
        }
        __syncthreads();

        float acc[4][4];
#pragma unroll
        for (int i = 0; i < 4; i++)
#pragma unroll
            for (int j = 0; j < 4; j++) acc[i][j] = 0.f;

#pragma unroll 16
        for (int k = 0; k < 64; k++) {
            float4 xv = *(const float4*)&XsT[k][rq * 4];
            float4 wv = *(const float4*)&Ws [k][cq * 4];
            acc[0][0] += xv.x*wv.x; acc[0][1] += xv.x*wv.y; acc[0][2] += xv.x*wv.z; acc[0][3] += xv.x*wv.w;
            acc[1][0] += xv.y*wv.x; acc[1][1] += xv.y*wv.y; acc[1][2] += xv.y*wv.z; acc[1][3] += xv.y*wv.w;
            acc[2][0] += xv.z*wv.x; acc[2][1] += xv.z*wv.y; acc[2][2] += xv.z*wv.z; acc[2][3] += xv.z*wv.w;
            acc[3][0] += xv.w*wv.x; acc[3][1] += xv.w*wv.y; acc[3][2] += xv.w*wv.z; acc[3][3] += xv.w*wv.w;
        }

        float a1v[4], a2v[4];
#pragma unroll
        for (int j = 0; j < 4; j++) {
            a1v[j] = __ldg(&avec[head * 128 + cq * 4 + j]);
            a2v[j] = __ldg(&avec[head * 128 + 64 + cq * 4 + j]);
        }
#pragma unroll
        for (int i = 0; i < 4; i++) {
            int R = R0 + rq * 4 + i;
            int g = R >> 11;
            int n = R & (NN - 1);
            int seg = g * HH + head;
            size_t base = ((size_t)seg * NN + n) * 64 + cq * 4;
            float4 v; v.x = acc[i][0]; v.y = acc[i][1]; v.z = acc[i][2]; v.w = acc[i][3];
            *(float4*)&g_Hbuf[base] = v;

            float p1 = acc[i][0]*a1v[0] + acc[i][1]*a1v[1] + acc[i][2]*a1v[2] + acc[i][3]*a1v[3];
            float p2 = acc[i][0]*a2v[0] + acc[i][1]*a2v[1] + acc[i][2]*a2v[2] + acc[i][3]*a2v[3];
#pragma unroll
            for (int off = 8; off; off >>= 1) {
                p1 += __shfl_down_sync(0xffffffffu, p1, off, 16);
                p2 += __shfl_down_sync(0xffffffffu, p2, off, 16);
            }
            if (cq == 0) {
                g_s1[seg * NN + n] = p1;
                g_s2[seg * NN + n] = p2;
            }
        }
    }
}

// ---------------- layer-2 GEMM (K = 256) ----------------
__global__ __launch_bounds__(256)
void gemm2_kernel(const float* __restrict__ Wmat,
                  const float* __restrict__ avec) {
    __shared__ float XsT[64][68];
    __shared__ float Ws [64][64];
    const int tid = threadIdx.x;
    const int R0  = blockIdx.x * 64;
    const int rq  = tid >> 4;
    const int cq  = tid & 15;

    float acc[4][4];
#pragma unroll
    for (int i = 0; i < 4; i++)
#pragma unroll
        for (int j = 0; j < 4; j++) acc[i][j] = 0.f;

    for (int kp = 0; kp < 256; kp += 64) {
        __syncthreads();
#pragma unroll
        for (int i = 0; i < 16; i++) {
            int idx = tid + i * 256;
            int r = idx >> 6, k = idx & 63;
            XsT[k][r] = g_XC[(size_t)(R0 + r) * 256 + kp + k];
        }
#pragma unroll
        for (int i = 0; i < 16; i++) {
            int idx = tid + i * 256;
            int k = idx >> 6, d = idx & 63;
            Ws[k][d] = Wmat[((size_t)kp + k) * 64 + d];
        }
        __syncthreads();
#pragma unroll 16
        for (int k = 0; k < 64; k++) {
            float4 xv = *(const float4*)&XsT[k][rq * 4];
            float4 wv = *(const float4*)&Ws [k][cq * 4];
            acc[0][0] += xv.x*wv.x; acc[0][1] += xv.x*wv.y; acc[0][2] += xv.x*wv.z; acc[0][3] += xv.x*wv.w;
            acc[1][0] += xv.y*wv.x; acc[1][1] += xv.y*wv.y; acc[1][2] += xv.y*wv.z; acc[1][3] += xv.y*wv.w;
            acc[2][0] += xv.z*wv.x; acc[2][1] += xv.z*wv.y; acc[2][2] += xv.z*wv.z; acc[2][3] += xv.z*wv.w;
            acc[3][0] += xv.w*wv.x; acc[3][1] += xv.w*wv.y; acc[3][2] += xv.w*wv.z; acc[3][3] += xv.w*wv.w;
        }
    }

    float a1v[4], a2v[4];
#pragma unroll
    for (int j = 0; j < 4; j++) {
        a1v[j] = __ldg(&avec[cq * 4 + j]);
        a2v[j] = __ldg(&avec[64 + cq * 4 + j]);
    }
#pragma unroll
    for (int i = 0; i < 4; i++) {
        int R = R0 + rq * 4 + i;
        int seg = R >> 11;
        int n = R & (NN - 1);
        size_t base = ((size_t)seg * NN + n) * 64 + cq * 4;
        float4 v; v.x = acc[i][0]; v.y = acc[i][1]; v.z = acc[i][2]; v.w = acc[i][3];
        *(float4*)&g_H2[base] = v;

        float p1 = acc[i][0]*a1v[0] + acc[i][1]*a1v[1] + acc[i][2]*a1v[2] + acc[i][3]*a1v[3];
        float p2 = acc[i][0]*a2v[0] + acc[i][1]*a2v[1] + acc[i][2]*a2v[2] + acc[i][3]*a2v[3];
#pragma unroll
        for (int off = 8; off; off >>= 1) {
            p1 += __shfl_down_sync(0xffffffffu, p1, off, 16);
            p2 += __shfl_down_sync(0xffffffffu, p2, off, 16);
        }
        if (cq == 0) {
            g_s1[seg * NN + n] = p1;
            g_s2[seg * NN + n] = p2;
        }
    }
}

// ---------------- bitonic sort: 1024 threads, one comparator each ----------------
__global__ __launch_bounds__(1024)
void sort_kernel() {
    __shared__ float key[NN];
    __shared__ int   idx[NN];
    const int seg = blockIdx.x, tid = threadIdx.x;

    key[tid]        = g_s2[seg * NN + tid];        idx[tid]        = tid;
    key[tid + 1024] = g_s2[seg * NN + tid + 1024]; idx[tid + 1024] = tid + 1024;

    for (int k = 2; k <= NN; k <<= 1) {
        for (int j = k >> 1; j > 0; j >>= 1) {
            __syncthreads();
            int i = ((tid & ~(j - 1)) << 1) | (tid & (j - 1));
            int p = i | j;
            bool up = ((i & k) == 0);
            float ka = key[i], kb = key[p];
            if ((ka > kb) == up) {
                key[i] = kb; key[p] = ka;
                int t = idx[i]; idx[i] = idx[p]; idx[p] = t;
            }
        }
    }
    __syncthreads();

    float smaxv = key[NN - 1];
#pragma unroll
    for (int u = 0; u < 2; u++) {
        int i = tid + u * 1024;
        float kk = key[i];
        g_sorted[seg * NN + i] = kk;
        g_perm  [seg * NN + i] = idx[i];
        g_wsuf  [seg * NN + i] = expf(kk - smaxv);
        g_wpre  [seg * NN + i] = expf(ALPHA_ * (kk - smaxv));
    }
    if (tid == 0) g_smax[seg] = smaxv;
}

// ---------------- pass 3a: per-chunk sums, BOTH halves per thread (one H load) ----------------
__global__ __launch_bounds__(64)
void pass3a_kernel(int layer) {
    const int seg = blockIdx.x, c = blockIdx.y, d = threadIdx.x;
    const float* __restrict__ Hmat = (layer == 1) ? g_Hbuf : g_H2;
    const int q0 = c * CL;

    __shared__ int   sp[CL];
    __shared__ float swA[CL], swB[CL];
    sp [d] = g_perm[seg * NN + q0 + d];
    swA[d] = g_wpre[seg * NN + q0 + d];
    swB[d] = g_wsuf[seg * NN + q0 + d];
    __syncthreads();

    const size_t segNN = (size_t)seg * NN;
    float accA = 0.f, accB = 0.f;
#pragma unroll 8
    for (int q = 0; q < CL; q++) {
        float h = __ldg(&Hmat[(segNN + sp[q]) * 64 + d]);
        accA += swA[q] * h;
        accB += swB[q] * h;
    }
    g_CT[(seg * CH + c) * 128 + d]      = accA;
    g_CT[(seg * CH + c) * 128 + 64 + d] = accB;
}

// ---------------- pass 3c: 2 chunks/block, float2 lanes, self-computed offsets ----------------
__global__ __launch_bounds__(128)
void pass3c_kernel(int layer) {
    const int seg = blockIdx.x, cb = blockIdx.y * NCPB, tid = threadIdx.x;
    const float* __restrict__ Hmat = (layer == 1) ? g_Hbuf : g_H2;

    __shared__ int   sp [NCPB * CL];
    __shared__ float swA[NCPB * CL], swB[NCPB * CL];
    __shared__ float tile[NCPB * CL * 64];   // 32KB

    sp [tid] = g_perm[seg * NN + cb * CL + tid];
    swA[tid] = g_wpre[seg * NN + cb * CL + tid];
    swB[tid] = g_wsuf[seg * NN + cb * CL + tid];
    __syncthreads();

    const size_t segNN = (size_t)seg * NN;
    {
        int rg = tid >> 4;
        int cq = tid & 15;
#pragma unroll
        for (int rr = 0; rr < NCPB * CL; rr += 8) {
            int r = rr + rg;
            const float4* src = (const float4*)&Hmat[(segNN + sp[r]) * 64];
            ((float4*)&tile[r * 64])[cq] = __ldg(&src[cq]);
        }
    }
    __syncthreads();

    const int ci   = tid >> 6;           // chunk within block
    const int half = (tid >> 5) & 1;     // 0 = A (forward), 1 = B (backward)
    const int d2   = (tid & 31) * 2;
    const int c    = cb + ci;
    const float* tl = &tile[ci * CL * 64];
    const float* w  = half ? &swB[ci * CL] : &swA[ci * CL];
    const size_t rowbase = ((size_t)seg * (NN + 1) + c * CL) * 64 + d2;

    // self-computed chunk offset from raw totals in g_CT
    float2 run = make_float2(0.f, 0.f);
    if (half == 0) {
        for (int cc = 0; cc < c; cc++) {
            float2 t = *(const float2*)&g_CT[(seg * CH + cc) * 128 + d2];
            run.x += t.x; run.y += t.y;
        }
    } else {
        for (int cc = c + 1; cc < CH; cc++) {
            float2 t = *(const float2*)&g_CT[(seg * CH + cc) * 128 + 64 + d2];
            run.x += t.x; run.y += t.y;
        }
    }

    if (half == 0) {   // forward exclusive prefix of wpre*h
#pragma unroll 8
        for (int t = 0; t < CL; t++) {
            *(float2*)&g_Ah[rowbase + (size_t)t * 64] = run;
            float2 h = *(const float2*)&tl[t * 64 + d2];
            run.x += w[t] * h.x;
            run.y += w[t] * h.y;
        }
        if (c == CH - 1)   // boundary row p == NN: full prefix total
            *(float2*)&g_Ah[((size_t)seg * (NN + 1) + NN) * 64 + d2] = run;
    } else {           // reverse inclusive suffix of wsuf*h
        if (c == CH - 1)   // boundary row p == NN: empty suffix
            *(float2*)&g_Bh[((size_t)seg * (NN + 1) + NN) * 64 + d2] = run;
#pragma unroll 8
        for (int t = CL - 1; t >= 0; t--) {
            float2 h = *(const float2*)&tl[t * 64 + d2];
            run.x += w[t] * h.x;
            run.y += w[t] * h.y;
            *(float2*)&g_Bh[rowbase + (size_t)t * 64] = run;
        }
    }
}

// ---------------- qprep: fused scalar scans (smem) + binary search per query ----------------
__global__ __launch_bounds__(1024)
void qprep_kernel() {
    const int seg = blockIdx.x, tid = threadIdx.x;
    const int lane = tid & 31, wid = tid >> 5;

    __shared__ float srt[NN];
    __shared__ float sA1[NN + 1];
    __shared__ float sB1[NN + 1];
    __shared__ float wxA[32], wxB[32];

    srt[tid]        = g_sorted[seg * NN + tid];
    srt[tid + 1024] = g_sorted[seg * NN + tid + 1024];

    const int j0 = tid * 2;
    float2 wa = *(const float2*)&g_wpre[seg * NN + j0];
    float2 wb = *(const float2*)&g_wsuf[seg * NN + j0];
    float sa = wa.x + wa.y;
    float sb = wb.x + wb.y;

    // warp inclusive prefix scan of sa
    float xa = sa;
#pragma unroll
    for (int off = 1; off < 32; off <<= 1) {
        float y = __shfl_up_sync(0xffffffffu, xa, off);
        if (lane >= off) xa += y;
    }
    float exA = xa - sa;
    // warp inclusive suffix scan of sb
    float xb = sb;
#pragma unroll
    for (int off = 1; off < 32; off <<= 1) {
        float y = __shfl_down_sync(0xffffffffu, xb, off);
        if (lane < 32 - off) xb += y;
    }
    float exB = xb - sb;

    if (lane == 31) wxA[wid] = xa;   // warp totals (temporarily)
    if (lane == 0)  wxB[wid] = xb;
    __syncthreads();
    if (wid == 0) {
        // scan the 32 warp totals with warp 0
        float va = wxA[lane];
        float xa2 = va;
#pragma unroll
        for (int off = 1; off < 32; off <<= 1) {
            float y = __shfl_up_sync(0xffffffffu, xa2, off);
            if (lane >= off) xa2 += y;
        }
        float vb = wxB[lane];
        float xb2 = vb;
#pragma unroll
        for (int off = 1; off < 32; off <<= 1) {
            float y = __shfl_down_sync(0xffffffffu, xb2, off);
            if (lane < 32 - off) xb2 += y;
        }
        __syncwarp();
        wxA[lane] = xa2 - va;        // exclusive prefix of warp totals
        wxB[lane] = xb2 - vb;        // exclusive suffix of warp totals
        if (lane == 31) sA1[NN] = xa2;   // grand total
        if (lane == 0)  sB1[NN] = 0.f;
    }
    __syncthreads();
    float oa = wxA[wid] + exA;
    float ob = wxB[wid] + exB;
    sA1[j0]     = oa;
    sA1[j0 + 1] = oa + wa.x;
    sB1[j0]     = ob + wb.x + wb.y;
    sB1[j0 + 1] = ob + wb.y;
    __syncthreads();

    const float smax = g_smax[seg];
#pragma unroll
    for (int u = 0; u < 2; u++) {
        int n = tid + u * 1024;
        float s1v = g_s1[seg * NN + n];
        float uu = s1v + smax;
        float m = (uu >= 0.f) ? uu : ALPHA_ * uu;
        float f1 = expf(uu - m);
        float f2 = expf(ALPHA_ * uu - m);
        float tau = -s1v;
        int lo = 0, hi = NN;
        while (lo < hi) {
            int mid = (lo + hi) >> 1;
            if (srt[mid] < tau) lo = mid + 1; else hi = mid;
        }
        int p = lo;
        float den = f1 * sB1[p] + f2 * sA1[p];
        g_qp[seg * NN + n] = p;
        g_qr[seg * NN + n] = make_float2(f2 / den, f1 / den);
    }
}

// ---------------- layer-1 combine: pure stream, elu -> XC ----------------
__global__ __launch_bounds__(256)
void combine1_kernel() {
    const int seg = blockIdx.y, tid = threadIdx.x;
    const int n  = blockIdx.x * 16 + (tid >> 4);
    const int d4 = (tid & 15) * 4;

    int    p = g_qp[seg * NN + n];
    float2 r = g_qr[seg * NN + n];
    size_t rb = ((size_t)seg * (NN + 1) + p) * 64 + d4;
    float4 a = *(const float4*)&g_Ah[rb];
    float4 b = *(const float4*)&g_Bh[rb];
    float4 o;
    o.x = r.y * b.x + r.x * a.x;
    o.y = r.y * b.y + r.x * a.y;
    o.z = r.y * b.z + r.x * a.z;
    o.w = r.y * b.w + r.x * a.w;
    o.x = (o.x > 0.f) ? o.x : expm1f(o.x);
    o.y = (o.y > 0.f) ? o.y : expm1f(o.y);
    o.z = (o.z > 0.f) ? o.z : expm1f(o.z);
    o.w = (o.w > 0.f) ? o.w : expm1f(o.w);

    int g = seg >> 2, h = seg & 3;
    *(float4*)&g_XC[((size_t)g * NN + n) * (HH * DD) + h * DD + d4] = o;
}

// ---------------- layer-2 combine: stream, elu -> log_softmax -> out ----------------
__global__ __launch_bounds__(256)
void combine2_kernel(float* __restrict__ out) {
    const int seg = blockIdx.y, tid = threadIdx.x;
    const int n  = blockIdx.x * 16 + (tid >> 4);
    const int d4 = (tid & 15) * 4;

    int    p = g_qp[seg * NN + n];
    float2 r = g_qr[seg * NN + n];
    size_t rb = ((size_t)seg * (NN + 1) + p) * 64 + d4;
    float4 a = *(const float4*)&g_Ah[rb];
    float4 b = *(const float4*)&g_Bh[rb];
    float4 o;
    o.x = r.y * b.x + r.x * a.x;
    o.y = r.y * b.y + r.x * a.y;
    o.z = r.y * b.z + r.x * a.z;
    o.w = r.y * b.w + r.x * a.w;
    o.x = (o.x > 0.f) ? o.x : expm1f(o.x);
    o.y = (o.y > 0.f) ? o.y : expm1f(o.y);
    o.z = (o.z > 0.f) ? o.z : expm1f(o.z);
    o.w = (o.w > 0.f) ? o.w : expm1f(o.w);

    float lm = fmaxf(fmaxf(o.x, o.y), fmaxf(o.z, o.w));
#pragma unroll
    for (int off = 8; off; off >>= 1)
        lm = fmaxf(lm, __shfl_xor_sync(0xffffffffu, lm, off, 16));
    float ls = expf(o.x - lm) + expf(o.y - lm) + expf(o.z - lm) + expf(o.w - lm);
#pragma unroll
    for (int off = 8; off; off >>= 1)
        ls += __shfl_xor_sync(0xffffffffu, ls, off, 16);
    float sub = lm + logf(ls);

    float4 w;
    w.x = o.x - sub; w.y = o.y - sub; w.z = o.z - sub; w.w = o.w - sub;
    *(float4*)&out[((size_t)seg * NN + n) * DD + d4] = w;
}

// ---------------- launch ----------------
extern "C" void kernel_launch(void* const* d_in, const int* in_sizes, int n_in,
                              void* d_out, int out_size) {
    const float* h_states = (const float*)d_in[0];
    const float* W_heads  = (const float*)d_in[1];
    const float* a_heads  = (const float*)d_in[2];
    const float* W_out    = (const float*)d_in[3];
    const float* a_out    = (const float*)d_in[4];
    float* out = (float*)d_out;

    // ---- layer 1 ----
    gemm1_kernel<<<BB * NN / 64, 256>>>(h_states, W_heads, a_heads);
    sort_kernel<<<SEG1, 1024>>>();
    pass3a_kernel<<<dim3(SEG1, CH), 64>>>(1);
    pass3c_kernel<<<dim3(SEG1, CH / NCPB), 128>>>(1);
    qprep_kernel<<<SEG1, 1024>>>();
    combine1_kernel<<<dim3(NN / 16, SEG1), 256>>>();

    // ---- layer 2 ----
    gemm2_kernel<<<BB * NN / 64, 256>>>(W_out, a_out);
    sort_kernel<<<BB, 1024>>>();
    pass3a_kernel<<<dim3(BB, CH), 64>>>(2);
    pass3c_kernel<<<dim3(BB, CH / NCPB), 128>>>(2);
    qprep_kernel<<<BB, 1024>>>();
    combine2_kernel<<<dim3(NN / 16, BB), 256>>>(out);
}

// round 14
// speedup vs baseline: 5.8575x; 1.0430x over previous
#include <cuda_runtime.h>
#include <math.h>

#define NN   2048
#define BB   8
#define HH   4
#define DD   64
#define SEG1 (BB*HH)     // 32 segments in layer 1
#define CH   64          // scan chunks per segment
#define CL   (NN/CH)     // 32 elements per chunk
#define NCPB 2           // chunks per pass3c block
#define ALPHA_ 0.2f

// ---------------- scratch (static __device__, no allocation) ----------------
__device__ float g_Hbuf [SEG1 * NN * DD];
__device__ float g_H2   [BB   * NN * DD];
__device__ float g_s1   [SEG1 * NN];
__device__ float g_s2   [SEG1 * NN];
__device__ float g_sorted[SEG1 * NN];
__device__ int   g_perm [SEG1 * NN];
__device__ float g_wpre [SEG1 * NN];
__device__ float g_wsuf [SEG1 * NN];
__device__ float g_smax [SEG1];
__device__ float g_CT   [SEG1 * CH * 128];     // raw chunk totals (A: 0-63, B: 64-127)
__device__ float g_Ah   [SEG1 * (NN+1) * DD];
__device__ float g_Bh   [SEG1 * (NN+1) * DD];
__device__ float g_XC   [BB * NN * HH * DD];
__device__ int   g_qp   [SEG1 * NN];
__device__ float2 g_qr  [SEG1 * NN];

// ---------------- layer-1 GEMM: all 4 heads per block, X tile reused ----------------
__global__ __launch_bounds__(256)
void gemm1_kernel(const float* __restrict__ X,
                  const float* __restrict__ Wmat,
                  const float* __restrict__ avec) {
    __shared__ float XsT[64][68];
    __shared__ float Ws [64][64];
    const int tid = threadIdx.x;
    const int R0  = blockIdx.x * 64;
    const int rq  = tid >> 4;
    const int cq  = tid & 15;

#pragma unroll
    for (int i = 0; i < 16; i++) {
        int idx = tid + i * 256;
        int r = idx >> 6, k = idx & 63;
        XsT[k][r] = X[(size_t)(R0 + r) * 64 + k];
    }

    for (int head = 0; head < HH; head++) {
        __syncthreads();
#pragma unroll
        for (int i = 0; i < 16; i++) {
            int idx = tid + i * 256;
            int k = idx >> 6, d = idx & 63;
            Ws[k][d] = Wmat[((size_t)head * 64 + k) * 64 + d];
        }
        __syncthreads();

        float acc[4][4];
#pragma unroll
        for (int i = 0; i < 4; i++)
#pragma unroll
            for (int j = 0; j < 4; j++) acc[i][j] = 0.f;

#pragma unroll 16
        for (int k = 0; k < 64; k++) {
            float4 xv = *(const float4*)&XsT[k][rq * 4];
            float4 wv = *(const float4*)&Ws [k][cq * 4];
            acc[0][0] += xv.x*wv.x; acc[0][1] += xv.x*wv.y; acc[0][2] += xv.x*wv.z; acc[0][3] += xv.x*wv.w;
            acc[1][0] += xv.y*wv.x; acc[1][1] += xv.y*wv.y; acc[1][2] += xv.y*wv.z; acc[1][3] += xv.y*wv.w;
            acc[2][0] += xv.z*wv.x; acc[2][1] += xv.z*wv.y; acc[2][2] += xv.z*wv.z; acc[2][3] += xv.z*wv.w;
            acc[3][0] += xv.w*wv.x; acc[3][1] += xv.w*wv.y; acc[3][2] += xv.w*wv.z; acc[3][3] += xv.w*wv.w;
        }

        float a1v[4], a2v[4];
#pragma unroll
        for (int j = 0; j < 4; j++) {
            a1v[j] = __ldg(&avec[head * 128 + cq * 4 + j]);
            a2v[j] = __ldg(&avec[head * 128 + 64 + cq * 4 + j]);
        }
#pragma unroll
        for (int i = 0; i < 4; i++) {
            int R = R0 + rq * 4 + i;
            int g = R >> 11;
            int n = R & (NN - 1);
            int seg = g * HH + head;
            size_t base = ((size_t)seg * NN + n) * 64 + cq * 4;
            float4 v; v.x = acc[i][0]; v.y = acc[i][1]; v.z = acc[i][2]; v.w = acc[i][3];
            *(float4*)&g_Hbuf[base] = v;

            float p1 = acc[i][0]*a1v[0] + acc[i][1]*a1v[1] + acc[i][2]*a1v[2] + acc[i][3]*a1v[3];
            float p2 = acc[i][0]*a2v[0] + acc[i][1]*a2v[1] + acc[i][2]*a2v[2] + acc[i][3]*a2v[3];
#pragma unroll
            for (int off = 8; off; off >>= 1) {
                p1 += __shfl_down_sync(0xffffffffu, p1, off, 16);
                p2 += __shfl_down_sync(0xffffffffu, p2, off, 16);
            }
            if (cq == 0) {
                g_s1[seg * NN + n] = p1;
                g_s2[seg * NN + n] = p2;
            }
        }
    }
}

// ---------------- layer-2 GEMM (K = 256) ----------------
__global__ __launch_bounds__(256)
void gemm2_kernel(const float* __restrict__ Wmat,
                  const float* __restrict__ avec) {
    __shared__ float XsT[64][68];
    __shared__ float Ws [64][64];
    const int tid = threadIdx.x;
    const int R0  = blockIdx.x * 64;
    const int rq  = tid >> 4;
    const int cq  = tid & 15;

    float acc[4][4];
#pragma unroll
    for (int i = 0; i < 4; i++)
#pragma unroll
        for (int j = 0; j < 4; j++) acc[i][j] = 0.f;

    for (int kp = 0; kp < 256; kp += 64) {
        __syncthreads();
#pragma unroll
        for (int i = 0; i < 16; i++) {
            int idx = tid + i * 256;
            int r = idx >> 6, k = idx & 63;
            XsT[k][r] = g_XC[(size_t)(R0 + r) * 256 + kp + k];
        }
#pragma unroll
        for (int i = 0; i < 16; i++) {
            int idx = tid + i * 256;
            int k = idx >> 6, d = idx & 63;
            Ws[k][d] = Wmat[((size_t)kp + k) * 64 + d];
        }
        __syncthreads();
#pragma unroll 16
        for (int k = 0; k < 64; k++) {
            float4 xv = *(const float4*)&XsT[k][rq * 4];
            float4 wv = *(const float4*)&Ws [k][cq * 4];
            acc[0][0] += xv.x*wv.x; acc[0][1] += xv.x*wv.y; acc[0][2] += xv.x*wv.z; acc[0][3] += xv.x*wv.w;
            acc[1][0] += xv.y*wv.x; acc[1][1] += xv.y*wv.y; acc[1][2] += xv.y*wv.z; acc[1][3] += xv.y*wv.w;
            acc[2][0] += xv.z*wv.x; acc[2][1] += xv.z*wv.y; acc[2][2] += xv.z*wv.z; acc[2][3] += xv.z*wv.w;
            acc[3][0] += xv.w*wv.x; acc[3][1] += xv.w*wv.y; acc[3][2] += xv.w*wv.z; acc[3][3] += xv.w*wv.w;
        }
    }

    float a1v[4], a2v[4];
#pragma unroll
    for (int j = 0; j < 4; j++) {
        a1v[j] = __ldg(&avec[cq * 4 + j]);
        a2v[j] = __ldg(&avec[64 + cq * 4 + j]);
    }
#pragma unroll
    for (int i = 0; i < 4; i++) {
        int R = R0 + rq * 4 + i;
        int seg = R >> 11;
        int n = R & (NN - 1);
        size_t base = ((size_t)seg * NN + n) * 64 + cq * 4;
        float4 v; v.x = acc[i][0]; v.y = acc[i][1]; v.z = acc[i][2]; v.w = acc[i][3];
        *(float4*)&g_H2[base] = v;

        float p1 = acc[i][0]*a1v[0] + acc[i][1]*a1v[1] + acc[i][2]*a1v[2] + acc[i][3]*a1v[3];
        float p2 = acc[i][0]*a2v[0] + acc[i][1]*a2v[1] + acc[i][2]*a2v[2] + acc[i][3]*a2v[3];
#pragma unroll
        for (int off = 8; off; off >>= 1) {
            p1 += __shfl_down_sync(0xffffffffu, p1, off, 16);
            p2 += __shfl_down_sync(0xffffffffu, p2, off, 16);
        }
        if (cq == 0) {
            g_s1[seg * NN + n] = p1;
            g_s2[seg * NN + n] = p2;
        }
    }
}

// ---------------- bitonic sort: 1024 threads, one comparator each ----------------
__global__ __launch_bounds__(1024)
void sort_kernel() {
    __shared__ float key[NN];
    __shared__ int   idx[NN];
    const int seg = blockIdx.x, tid = threadIdx.x;

    key[tid]        = g_s2[seg * NN + tid];        idx[tid]        = tid;
    key[tid + 1024] = g_s2[seg * NN + tid + 1024]; idx[tid + 1024] = tid + 1024;

    for (int k = 2; k <= NN; k <<= 1) {
        for (int j = k >> 1; j > 0; j >>= 1) {
            __syncthreads();
            int i = ((tid & ~(j - 1)) << 1) | (tid & (j - 1));
            int p = i | j;
            bool up = ((i & k) == 0);
            float ka = key[i], kb = key[p];
            if ((ka > kb) == up) {
                key[i] = kb; key[p] = ka;
                int t = idx[i]; idx[i] = idx[p]; idx[p] = t;
            }
        }
    }
    __syncthreads();

    float smaxv = key[NN - 1];
#pragma unroll
    for (int u = 0; u < 2; u++) {
        int i = tid + u * 1024;
        float kk = key[i];
        g_sorted[seg * NN + i] = kk;
        g_perm  [seg * NN + i] = idx[i];
        g_wsuf  [seg * NN + i] = expf(kk - smaxv);
        g_wpre  [seg * NN + i] = expf(ALPHA_ * (kk - smaxv));
    }
    if (tid == 0) g_smax[seg] = smaxv;
}

// ---------------- pass 3a: per-chunk sums, BOTH halves per thread (one H load) ----------------
__global__ __launch_bounds__(64)
void pass3a_kernel(int layer) {
    const int seg = blockIdx.x, c = blockIdx.y, d = threadIdx.x;
    const float* __restrict__ Hmat = (layer == 1) ? g_Hbuf : g_H2;
    const int q0 = c * CL;

    __shared__ int   sp[CL];
    __shared__ float swA[CL], swB[CL];
    if (d < CL) {
        sp [d] = g_perm[seg * NN + q0 + d];
        swA[d] = g_wpre[seg * NN + q0 + d];
        swB[d] = g_wsuf[seg * NN + q0 + d];
    }
    __syncthreads();

    const size_t segNN = (size_t)seg * NN;
    float accA = 0.f, accB = 0.f;
#pragma unroll 8
    for (int q = 0; q < CL; q++) {
        float h = __ldg(&Hmat[(segNN + sp[q]) * 64 + d]);
        accA += swA[q] * h;
        accB += swB[q] * h;
    }
    g_CT[(seg * CH + c) * 128 + d]      = accA;
    g_CT[(seg * CH + c) * 128 + 64 + d] = accB;
}

// ---------------- pass 3c: 2 chunks/block, float2 lanes, self-computed offsets ----------------
__global__ __launch_bounds__(128)
void pass3c_kernel(int layer) {
    const int seg = blockIdx.x, cb = blockIdx.y * NCPB, tid = threadIdx.x;
    const float* __restrict__ Hmat = (layer == 1) ? g_Hbuf : g_H2;

    __shared__ int   sp [NCPB * CL];
    __shared__ float swA[NCPB * CL], swB[NCPB * CL];
    __shared__ float tile[NCPB * CL * 64];   // 16KB

    if (tid < NCPB * CL) {
        sp [tid] = g_perm[seg * NN + cb * CL + tid];
        swA[tid] = g_wpre[seg * NN + cb * CL + tid];
        swB[tid] = g_wsuf[seg * NN + cb * CL + tid];
    }
    __syncthreads();

    const size_t segNN = (size_t)seg * NN;
    {
        int rg = tid >> 4;        // 0..7
        int cq = tid & 15;        // float4 slot
#pragma unroll
        for (int rr = 0; rr < NCPB * CL; rr += 8) {
            int r = rr + rg;
            const float4* src = (const float4*)&Hmat[(segNN + sp[r]) * 64];
            ((float4*)&tile[r * 64])[cq] = __ldg(&src[cq]);
        }
    }
    __syncthreads();

    const int ci   = tid >> 6;           // chunk within block
    const int half = (tid >> 5) & 1;     // 0 = A (forward), 1 = B (backward)
    const int d2   = (tid & 31) * 2;
    const int c    = cb + ci;
    const float* tl = &tile[ci * CL * 64];
    const float* w  = half ? &swB[ci * CL] : &swA[ci * CL];
    const size_t rowbase = ((size_t)seg * (NN + 1) + c * CL) * 64 + d2;

    // self-computed chunk offset from raw totals in g_CT
    float2 run = make_float2(0.f, 0.f);
    if (half == 0) {
        for (int cc = 0; cc < c; cc++) {
            float2 t = *(const float2*)&g_CT[(seg * CH + cc) * 128 + d2];
            run.x += t.x; run.y += t.y;
        }
    } else {
        for (int cc = c + 1; cc < CH; cc++) {
            float2 t = *(const float2*)&g_CT[(seg * CH + cc) * 128 + 64 + d2];
            run.x += t.x; run.y += t.y;
        }
    }

    if (half == 0) {   // forward exclusive prefix of wpre*h
#pragma unroll 8
        for (int t = 0; t < CL; t++) {
            *(float2*)&g_Ah[rowbase + (size_t)t * 64] = run;
            float2 h = *(const float2*)&tl[t * 64 + d2];
            run.x += w[t] * h.x;
            run.y += w[t] * h.y;
        }
        if (c == CH - 1)   // boundary row p == NN: full prefix total
            *(float2*)&g_Ah[((size_t)seg * (NN + 1) + NN) * 64 + d2] = run;
    } else {           // reverse inclusive suffix of wsuf*h
        if (c == CH - 1)   // boundary row p == NN: empty suffix
            *(float2*)&g_Bh[((size_t)seg * (NN + 1) + NN) * 64 + d2] = run;
#pragma unroll 8
        for (int t = CL - 1; t >= 0; t--) {
            float2 h = *(const float2*)&tl[t * 64 + d2];
            run.x += w[t] * h.x;
            run.y += w[t] * h.y;
            *(float2*)&g_Bh[rowbase + (size_t)t * 64] = run;
        }
    }
}

// ---------------- qprep: fused scalar scans (smem) + binary search per query ----------------
__global__ __launch_bounds__(1024)
void qprep_kernel() {
    const int seg = blockIdx.x, tid = threadIdx.x;
    const int lane = tid & 31, wid = tid >> 5;

    __shared__ float srt[NN];
    __shared__ float sA1[NN + 1];
    __shared__ float sB1[NN + 1];
    __shared__ float wxA[32], wxB[32];

    srt[tid]        = g_sorted[seg * NN + tid];
    srt[tid + 1024] = g_sorted[seg * NN + tid + 1024];

    const int j0 = tid * 2;
    float2 wa = *(const float2*)&g_wpre[seg * NN + j0];
    float2 wb = *(const float2*)&g_wsuf[seg * NN + j0];
    float sa = wa.x + wa.y;
    float sb = wb.x + wb.y;

    float xa = sa;
#pragma unroll
    for (int off = 1; off < 32; off <<= 1) {
        float y = __shfl_up_sync(0xffffffffu, xa, off);
        if (lane >= off) xa += y;
    }
    float exA = xa - sa;
    float xb = sb;
#pragma unroll
    for (int off = 1; off < 32; off <<= 1) {
        float y = __shfl_down_sync(0xffffffffu, xb, off);
        if (lane < 32 - off) xb += y;
    }
    float exB = xb - sb;

    if (lane == 31) wxA[wid] = xa;
    if (lane == 0)  wxB[wid] = xb;
    __syncthreads();
    if (wid == 0) {
        float va = wxA[lane];
        float xa2 = va;
#pragma unroll
        for (int off = 1; off < 32; off <<= 1) {
            float y = __shfl_up_sync(0xffffffffu, xa2, off);
            if (lane >= off) xa2 += y;
        }
        float vb = wxB[lane];
        float xb2 = vb;
#pragma unroll
        for (int off = 1; off < 32; off <<= 1) {
            float y = __shfl_down_sync(0xffffffffu, xb2, off);
            if (lane < 32 - off) xb2 += y;
        }
        __syncwarp();
        wxA[lane] = xa2 - va;
        wxB[lane] = xb2 - vb;
        if (lane == 31) sA1[NN] = xa2;
        if (lane == 0)  sB1[NN] = 0.f;
    }
    __syncthreads();
    float oa = wxA[wid] + exA;
    float ob = wxB[wid] + exB;
    sA1[j0]     = oa;
    sA1[j0 + 1] = oa + wa.x;
    sB1[j0]     = ob + wb.x + wb.y;
    sB1[j0 + 1] = ob + wb.y;
    __syncthreads();

    const float smax = g_smax[seg];
#pragma unroll
    for (int u = 0; u < 2; u++) {
        int n = tid + u * 1024;
        float s1v = g_s1[seg * NN + n];
        float uu = s1v + smax;
        float m = (uu >= 0.f) ? uu : ALPHA_ * uu;
        float f1 = expf(uu - m);
        float f2 = expf(ALPHA_ * uu - m);
        float tau = -s1v;
        int lo = 0, hi = NN;
        while (lo < hi) {
            int mid = (lo + hi) >> 1;
            if (srt[mid] < tau) lo = mid + 1; else hi = mid;
        }
        int p = lo;
        float den = f1 * sB1[p] + f2 * sA1[p];
        g_qp[seg * NN + n] = p;
        g_qr[seg * NN + n] = make_float2(f2 / den, f1 / den);
    }
}

// ---------------- layer-1 combine: pure stream, elu -> XC ----------------
__global__ __launch_bounds__(256)
void combine1_kernel() {
    const int seg = blockIdx.y, tid = threadIdx.x;
    const int n  = blockIdx.x * 16 + (tid >> 4);
    const int d4 = (tid & 15) * 4;

    int    p = g_qp[seg * NN + n];
    float2 r = g_qr[seg * NN + n];
    size_t rb = ((size_t)seg * (NN + 1) + p) * 64 + d4;
    float4 a = *(const float4*)&g_Ah[rb];
    float4 b = *(const float4*)&g_Bh[rb];
    float4 o;
    o.x = r.y * b.x + r.x * a.x;
    o.y = r.y * b.y + r.x * a.y;
    o.z = r.y * b.z + r.x * a.z;
    o.w = r.y * b.w + r.x * a.w;
    o.x = (o.x > 0.f) ? o.x : expm1f(o.x);
    o.y = (o.y > 0.f) ? o.y : expm1f(o.y);
    o.z = (o.z > 0.f) ? o.z : expm1f(o.z);
    o.w = (o.w > 0.f) ? o.w : expm1f(o.w);

    int g = seg >> 2, h = seg & 3;
    *(float4*)&g_XC[((size_t)g * NN + n) * (HH * DD) + h * DD + d4] = o;
}

// ---------------- layer-2 combine: stream, elu -> log_softmax -> out ----------------
__global__ __launch_bounds__(256)
void combine2_kernel(float* __restrict__ out) {
    const int seg = blockIdx.y, tid = threadIdx.x;
    const int n  = blockIdx.x * 16 + (tid >> 4);
    const int d4 = (tid & 15) * 4;

    int    p = g_qp[seg * NN + n];
    float2 r = g_qr[seg * NN + n];
    size_t rb = ((size_t)seg * (NN + 1) + p) * 64 + d4;
    float4 a = *(const float4*)&g_Ah[rb];
    float4 b = *(const float4*)&g_Bh[rb];
    float4 o;
    o.x = r.y * b.x + r.x * a.x;
    o.y = r.y * b.y + r.x * a.y;
    o.z = r.y * b.z + r.x * a.z;
    o.w = r.y * b.w + r.x * a.w;
    o.x = (o.x > 0.f) ? o.x : expm1f(o.x);
    o.y = (o.y > 0.f) ? o.y : expm1f(o.y);
    o.z = (o.z > 0.f) ? o.z : expm1f(o.z);
    o.w = (o.w > 0.f) ? o.w : expm1f(o.w);

    float lm = fmaxf(fmaxf(o.x, o.y), fmaxf(o.z, o.w));
#pragma unroll
    for (int off = 8; off; off >>= 1)
        lm = fmaxf(lm, __shfl_xor_sync(0xffffffffu, lm, off, 16));
    float ls = expf(o.x - lm) + expf(o.y - lm) + expf(o.z - lm) + expf(o.w - lm);
#pragma unroll
    for (int off = 8; off; off >>= 1)
        ls += __shfl_xor_sync(0xffffffffu, ls, off, 16);
    float sub = lm + logf(ls);

    float4 w;
    w.x = o.x - sub; w.y = o.y - sub; w.z = o.z - sub; w.w = o.w - sub;
    *(float4*)&out[((size_t)seg * NN + n) * DD + d4] = w;
}

// ---------------- launch ----------------
extern "C" void kernel_launch(void* const* d_in, const int* in_sizes, int n_in,
                              void* d_out, int out_size) {
    const float* h_states = (const float*)d_in[0];
    const float* W_heads  = (const float*)d_in[1];
    const float* a_heads  = (const float*)d_in[2];
    const float* W_out    = (const float*)d_in[3];
    const float* a_out    = (const float*)d_in[4];
    float* out = (float*)d_out;

    // ---- layer 1 ----
    gemm1_kernel<<<BB * NN / 64, 256>>>(h_states, W_heads, a_heads);
    sort_kernel<<<SEG1, 1024>>>();
    pass3a_kernel<<<dim3(SEG1, CH), 64>>>(1);
    pass3c_kernel<<<dim3(SEG1, CH / NCPB), 128>>>(1);
    qprep_kernel<<<SEG1, 1024>>>();
    combine1_kernel<<<dim3(NN / 16, SEG1), 256>>>();

    // ---- layer 2 ----
    gemm2_kernel<<<BB * NN / 64, 256>>>(W_out, a_out);
    sort_kernel<<<BB, 1024>>>();
    pass3a_kernel<<<dim3(BB, CH), 64>>>(2);
    pass3c_kernel<<<dim3(BB, CH / NCPB), 128>>>(2);
    qprep_kernel<<<BB, 1024>>>();
    combine2_kernel<<<dim3(NN / 16, BB), 256>>>(out);
}